// round 12
// baseline (speedup 1.0000x reference)
#include <cuda_runtime.h>
#include <cuda_bf16.h>
#include <cuda_fp16.h>
#include <math.h>
#include <stdint.h>

// ---------------------------------------------------------------------------
// MultilayerGRU: B=32, S=512, I=H=O=1024, L=2
// R12: R11 (proven 10.15ms) + hierarchical grid barrier: 128 arrivals go to
//      8 spread L2 sub-counters (16 each) then a root (8) — cuts the
//      single-address atomic serialization (~2.3us) to ~0.9us per barrier.
//      Numerics unchanged from R11.
// ---------------------------------------------------------------------------

#define B_  32
#define S_  512
#define IN_ 1024
#define H_  1024
#define OUT_ 1024
#define L_  2
#define M_  (B_ * S_)      /* 16384 */
#define N3_ (3 * H_)       /* 3072  */
#define NBLK 128

// ---------------- device scratch ------------------------------------------
__device__ float g_gx[(size_t)M_ * N3_];   // x-projections for current layer
__device__ float g_h[B_ * H_];             // fp32 master hidden state
__device__ float g_z[B_ * H_];             // z gate

__device__ __align__(16) unsigned short g_hf[B_ * H_];    // h fp16
__device__ __align__(16) unsigned short g_rhf[B_ * H_];   // r*h fp16

// bf16 hi/lo operand buffers (GEMM path)
__device__ __align__(16) unsigned short g_xh[(size_t)M_ * IN_],  g_xl[(size_t)M_ * IN_];
__device__ __align__(16) unsigned short g_seqh[(size_t)M_ * H_], g_seql[(size_t)M_ * H_];
__device__ __align__(16) unsigned short g_wzxh[(size_t)L_ * H_ * IN_], g_wzxl[(size_t)L_ * H_ * IN_];
__device__ __align__(16) unsigned short g_wrxh[(size_t)L_ * H_ * IN_], g_wrxl[(size_t)L_ * H_ * IN_];
__device__ __align__(16) unsigned short g_wgxh[(size_t)L_ * H_ * IN_], g_wgxl[(size_t)L_ * H_ * IN_];
__device__ __align__(16) unsigned short g_woh[(size_t)OUT_ * H_],      g_wol[(size_t)OUT_ * H_];

// fp16 recurrence weights
__device__ __align__(16) unsigned short g_wzhf[(size_t)L_ * H_ * H_];
__device__ __align__(16) unsigned short g_wrhf[(size_t)L_ * H_ * H_];
__device__ __align__(16) unsigned short g_wghf[(size_t)L_ * H_ * H_];

// hierarchical grid barrier: 8 sub-counters (512B apart) + root + gen
__device__ unsigned g_cnt[8 * 128];        // use indices i*128
__device__ unsigned g_root;
__device__ volatile unsigned g_gen;

__device__ __forceinline__ void grid_sync_tree(unsigned tgt, int grp) {
    __syncthreads();
    if (threadIdx.x == 0) {
        __threadfence();
        if (atomicAdd(&g_cnt[grp * 128], 1u) == 15u) {
            if (atomicAdd(&g_root, 1u) == 7u) {
#pragma unroll
                for (int i = 0; i < 8; i++) g_cnt[i * 128] = 0;
                g_root = 0;
                __threadfence();
                g_gen = tgt;
            }
        }
        while (g_gen < tgt) { }
        __threadfence();
    }
    __syncthreads();
}

// ---------------------------------------------------------------------------
__device__ __forceinline__ void split1(float v, unsigned short& h, unsigned short& l) {
    __nv_bfloat16 hb = __float2bfloat16(v);
    float r = v - __bfloat162float(hb);
    __nv_bfloat16 lb = __float2bfloat16(r);
    h = __bfloat16_as_ushort(hb);
    l = __bfloat16_as_ushort(lb);
}

// mma.sync m16n8k16 row.col, bf16 and fp16 flavors
__device__ __forceinline__ void mma_bf16(float* c, const uint32_t* a, const uint32_t* b) {
    asm volatile(
        "mma.sync.aligned.m16n8k16.row.col.f32.bf16.bf16.f32 "
        "{%0,%1,%2,%3}, {%4,%5,%6,%7}, {%8,%9}, {%0,%1,%2,%3};"
        : "+f"(c[0]), "+f"(c[1]), "+f"(c[2]), "+f"(c[3])
        : "r"(a[0]), "r"(a[1]), "r"(a[2]), "r"(a[3]), "r"(b[0]), "r"(b[1]));
}

__device__ __forceinline__ void mma_f16(float* c, const uint32_t* a, const uint32_t* b) {
    asm volatile(
        "mma.sync.aligned.m16n8k16.row.col.f32.f16.f16.f32 "
        "{%0,%1,%2,%3}, {%4,%5,%6,%7}, {%8,%9}, {%0,%1,%2,%3};"
        : "+f"(c[0]), "+f"(c[1]), "+f"(c[2]), "+f"(c[3])
        : "r"(a[0]), "r"(a[1]), "r"(a[2]), "r"(a[3]), "r"(b[0]), "r"(b[1]));
}

__device__ __forceinline__ float sigmoidf_(float x) {
    return 1.f / (1.f + expf(-x));
}

// ---------------------------------------------------------------------------
// x[b][t][i] -> hi/lo bf16 [t*B+b][i]
// ---------------------------------------------------------------------------
__global__ void k_transpose_x(const float* __restrict__ x) {
    int row = blockIdx.x;
    int t = row / B_;
    int b = row % B_;
    const float4* src = (const float4*)(x + ((size_t)b * S_ + t) * IN_);
    ushort4* dh = (ushort4*)(g_xh + (size_t)row * IN_);
    ushort4* dl = (ushort4*)(g_xl + (size_t)row * IN_);
    for (int i = threadIdx.x; i < IN_ / 4; i += blockDim.x) {
        float4 v = src[i];
        ushort4 h, l;
        split1(v.x, h.x, l.x);
        split1(v.y, h.y, l.y);
        split1(v.z, h.z, l.z);
        split1(v.w, h.w, l.w);
        dh[i] = h;
        dl[i] = l;
    }
}

// ---------------------------------------------------------------------------
// weight splits
// ---------------------------------------------------------------------------
__global__ void k_split(const float* __restrict__ src, int wsel, int n4) {
    int i = blockIdx.x * blockDim.x + threadIdx.x;
    if (i >= n4) return;
    unsigned short* hi;
    unsigned short* lo;
    switch (wsel) {
        case 0: hi = g_wzxh; lo = g_wzxl; break;
        case 1: hi = g_wrxh; lo = g_wrxl; break;
        case 2: hi = g_wgxh; lo = g_wgxl; break;
        default: hi = g_woh;  lo = g_wol; break;
    }
    float4 v = ((const float4*)src)[i];
    ushort4 h, l;
    split1(v.x, h.x, l.x);
    split1(v.y, h.y, l.y);
    split1(v.z, h.z, l.z);
    split1(v.w, h.w, l.w);
    ((ushort4*)hi)[i] = h;
    ((ushort4*)lo)[i] = l;
}

__global__ void k_split16(const float* __restrict__ src, int wsel, int n4) {
    int i = blockIdx.x * blockDim.x + threadIdx.x;
    if (i >= n4) return;
    float4 v = ((const float4*)src)[i];
    unsigned short* hi = (wsel == 0) ? g_wzhf : (wsel == 1) ? g_wrhf : g_wghf;
    ushort4 h;
    h.x = __half_as_ushort(__float2half(v.x));
    h.y = __half_as_ushort(__float2half(v.y));
    h.z = __half_as_ushort(__float2half(v.z));
    h.w = __half_as_ushort(__float2half(v.w));
    ((ushort4*)hi)[i] = h;
}

// ---------------------------------------------------------------------------
// k_prep: g_h / g_hf from h0[b][layer][:]; reset barrier state.
// ---------------------------------------------------------------------------
__global__ void k_prep(const float* __restrict__ h0, int layer) {
    int idx = blockIdx.x * blockDim.x + threadIdx.x;  // [0, B*H)
    if (idx < 8) g_cnt[idx * 128] = 0;
    if (idx == 8) g_root = 0;
    if (idx == 9) g_gen = 0;
    int b = idx / H_;
    int c = idx % H_;
    float v = h0[((size_t)b * L_ + layer) * H_ + c];
    g_h[idx] = v;
    g_hf[idx] = __half_as_ushort(__float2half(v));
}

// ---------------------------------------------------------------------------
// HMMA split-bf16 GEMM (unchanged, proven).
// ---------------------------------------------------------------------------
#define HMP 40

__global__ void __launch_bounds__(256) k_hmma(
    int asel, int wsel, int woff,
    const float* __restrict__ bias, float* __restrict__ Cout,
    int ldc, int col0, int permC)
{
    __shared__ __align__(16) unsigned short As_h[128 * HMP];
    __shared__ __align__(16) unsigned short As_l[128 * HMP];
    __shared__ __align__(16) unsigned short Bs_h[64 * HMP];
    __shared__ __align__(16) unsigned short Bs_l[64 * HMP];

    const int tid = threadIdx.x;
    const int m0 = blockIdx.y * 128, n0 = blockIdx.x * 64;

    const unsigned short* Ah = asel ? g_seqh : g_xh;
    const unsigned short* Al = asel ? g_seql : g_xl;
    const unsigned short* Wh;
    const unsigned short* Wl;
    switch (wsel) {
        case 0: Wh = g_wzxh; Wl = g_wzxl; break;
        case 1: Wh = g_wrxh; Wl = g_wrxl; break;
        case 2: Wh = g_wgxh; Wl = g_wgxl; break;
        default: Wh = g_woh; Wl = g_wol; break;
    }
    Wh += woff; Wl += woff;

    const int ar0 = (2 * tid) >> 2,     au0 = (2 * tid) & 3;
    const int ar1 = (2 * tid + 1) >> 2, au1 = (2 * tid + 1) & 3;
    const int br  = tid >> 2,           bu  = tid & 3;

    const int warp = tid >> 5, lane = tid & 31;
    const int g = lane >> 2, tg = lane & 3;
    const int wm = warp >> 1, wn = warp & 1;

    float acc[2][4][4];
#pragma unroll
    for (int mt = 0; mt < 2; mt++)
#pragma unroll
        for (int nt = 0; nt < 4; nt++)
#pragma unroll
            for (int i = 0; i < 4; i++) acc[mt][nt][i] = 0.f;

    const uint32_t* Awh = (const uint32_t*)As_h;
    const uint32_t* Awl = (const uint32_t*)As_l;
    const uint32_t* Bwh = (const uint32_t*)Bs_h;
    const uint32_t* Bwl = (const uint32_t*)Bs_l;

    uint4 vah0, vah1, val0, val1, vbh, vbl;
    vah0 = *(const uint4*)(Ah + (size_t)(m0 + ar0) * 1024 + au0 * 8);
    vah1 = *(const uint4*)(Ah + (size_t)(m0 + ar1) * 1024 + au1 * 8);
    val0 = *(const uint4*)(Al + (size_t)(m0 + ar0) * 1024 + au0 * 8);
    val1 = *(const uint4*)(Al + (size_t)(m0 + ar1) * 1024 + au1 * 8);
    vbh  = *(const uint4*)(Wh + (size_t)(n0 + br) * 1024 + bu * 8);
    vbl  = *(const uint4*)(Wl + (size_t)(n0 + br) * 1024 + bu * 8);

    for (int kc = 0; kc < 32; kc++) {
        __syncthreads();
        *(uint4*)(As_h + ar0 * HMP + au0 * 8) = vah0;
        *(uint4*)(As_h + ar1 * HMP + au1 * 8) = vah1;
        *(uint4*)(As_l + ar0 * HMP + au0 * 8) = val0;
        *(uint4*)(As_l + ar1 * HMP + au1 * 8) = val1;
        *(uint4*)(Bs_h + br * HMP + bu * 8) = vbh;
        *(uint4*)(Bs_l + br * HMP + bu * 8) = vbl;
        if (kc + 1 < 32) {
            int ko = (kc + 1) * 32;
            vah0 = *(const uint4*)(Ah + (size_t)(m0 + ar0) * 1024 + ko + au0 * 8);
            vah1 = *(const uint4*)(Ah + (size_t)(m0 + ar1) * 1024 + ko + au1 * 8);
            val0 = *(const uint4*)(Al + (size_t)(m0 + ar0) * 1024 + ko + au0 * 8);
            val1 = *(const uint4*)(Al + (size_t)(m0 + ar1) * 1024 + ko + au1 * 8);
            vbh  = *(const uint4*)(Wh + (size_t)(n0 + br) * 1024 + ko + bu * 8);
            vbl  = *(const uint4*)(Wl + (size_t)(n0 + br) * 1024 + ko + bu * 8);
        }
        __syncthreads();

#pragma unroll
        for (int ks = 0; ks < 2; ks++) {
            const int kw = ks * 8 + tg;
            uint32_t ahf[2][4], alf[2][4];
#pragma unroll
            for (int mt = 0; mt < 2; mt++) {
                int rb = (wm * 32 + mt * 16 + g) * 20 + kw;
                ahf[mt][0] = Awh[rb];
                ahf[mt][1] = Awh[rb + 160];
                ahf[mt][2] = Awh[rb + 4];
                ahf[mt][3] = Awh[rb + 164];
                alf[mt][0] = Awl[rb];
                alf[mt][1] = Awl[rb + 160];
                alf[mt][2] = Awl[rb + 4];
                alf[mt][3] = Awl[rb + 164];
            }
            uint32_t bhf[4][2], blf[4][2];
#pragma unroll
            for (int nt = 0; nt < 4; nt++) {
                int rb = (wn * 32 + nt * 8 + g) * 20 + kw;
                bhf[nt][0] = Bwh[rb];
                bhf[nt][1] = Bwh[rb + 4];
                blf[nt][0] = Bwl[rb];
                blf[nt][1] = Bwl[rb + 4];
            }
#pragma unroll
            for (int mt = 0; mt < 2; mt++)
#pragma unroll
                for (int nt = 0; nt < 4; nt++) {
                    mma_bf16(acc[mt][nt], ahf[mt], bhf[nt]);
                    mma_bf16(acc[mt][nt], ahf[mt], blf[nt]);
                    mma_bf16(acc[mt][nt], alf[mt], bhf[nt]);
                }
        }
    }

#pragma unroll
    for (int mt = 0; mt < 2; mt++) {
#pragma unroll
        for (int nt = 0; nt < 4; nt++) {
            int mrow = m0 + wm * 32 + mt * 16 + g;
            int ncol = n0 + wn * 32 + nt * 8 + tg * 2;
            float bx = bias[ncol], by = bias[ncol + 1];
#pragma unroll
            for (int half = 0; half < 2; half++) {
                int m = mrow + half * 8;
                float2 o;
                o.x = acc[mt][nt][half * 2 + 0] + bx;
                o.y = acc[mt][nt][half * 2 + 1] + by;
                float* dst;
                if (permC) {
                    int b = m & (B_ - 1);
                    int t = m >> 5;
                    dst = Cout + ((size_t)b * S_ + t) * ldc + ncol;
                } else {
                    dst = g_gx + (size_t)m * ldc + col0 + ncol;
                }
                *(float2*)dst = o;
            }
        }
    }
}

// ---------------------------------------------------------------------------
// fp16 tensor-core recurrence (R11 structure, NBLK=128, tree barrier).
// ---------------------------------------------------------------------------
#define SW_PW 516
#define TILE_B (32 * SW_PW * 4)            /* 66048 bytes tile buffer */
#define RED_STRIDE 18
#define RED_B (8 * 32 * RED_STRIDE * 4)    /* 18432 */
#define SMEMR (TILE_B + RED_B)             /* 84480 */

__device__ __forceinline__ void stage_one(
    const unsigned short* __restrict__ gsrc, uint32_t* __restrict__ s)
{
    const int tid = threadIdx.x;
#pragma unroll
    for (int rr = 0; rr < 2; rr++) {
        uint4 v[8];
#pragma unroll
        for (int it = 0; it < 8; it++) {
            int idx = tid + 256 * (rr * 8 + it);
            int row = idx >> 7;
            int u = idx & 127;
            v[it] = __ldcg((const uint4*)(gsrc + (size_t)row * H_) + u);
        }
#pragma unroll
        for (int it = 0; it < 8; it++) {
            int idx = tid + 256 * (rr * 8 + it);
            int row = idx >> 7;
            int u = idx & 127;
            *(uint4*)(s + row * SW_PW + u * 4) = v[it];
        }
    }
}

__global__ void __launch_bounds__(256, 1) k_gru_recur(
    int layer, float* __restrict__ hid_out)
{
    extern __shared__ char smem[];
    uint32_t* s_t0 = (uint32_t*)smem;                    // tile
    float*    red  = (float*)(smem + TILE_B);            // [8][32][18]

    const int tid = threadIdx.x;
    const int warp = tid >> 5, lane = tid & 31;
    const int g = lane >> 2, tg = lane & 3;
    const int grp = blockIdx.x & 7;          // barrier group

    // ---- ownership ----
    const int vc   = blockIdx.x * 16;        // [0,2048)
    const int gate = vc >> 10;               // 0=z, 1=r
    const int c1   = vc & 1023;
    const int goff = gate ? H_ : 0;
    const int cg0  = blockIdx.x * 8;         // phase-2 cols

    const size_t lw = (size_t)layer * H_ * H_;

    // ---- resident weight fragments (single fp16) ----
    uint32_t w1f[2][8][2];
    uint32_t w2f[8][2];
    {
        const unsigned short* W1 = gate ? g_wrhf : g_wzhf;
#pragma unroll
        for (int nt = 0; nt < 2; nt++)
#pragma unroll
            for (int ks = 0; ks < 8; ks++) {
                int row = c1 + nt * 8 + g;
                int kw = warp * 64 + ks * 8 + tg;
                const uint32_t* wr = (const uint32_t*)(W1 + lw + (size_t)row * H_);
                w1f[nt][ks][0] = wr[kw];
                w1f[nt][ks][1] = wr[kw + 4];
            }
#pragma unroll
        for (int ks = 0; ks < 8; ks++) {
            int row = cg0 + g;
            int kw = warp * 64 + ks * 8 + tg;
            const uint32_t* wr = (const uint32_t*)(g_wghf + lw + (size_t)row * H_);
            w2f[ks][0] = wr[kw];
            w2f[ks][1] = wr[kw + 4];
        }
    }

    // epilogue index maps
    const int e1b0 = tid >> 4,          e1c0 = tid & 15;
    const int e1b1 = (tid + 256) >> 4,  e1c1 = (tid + 256) & 15;
    const int e2b = tid >> 3, e2c = tid & 7;
    const int j2 = cg0 + e2c;

    // prefetch phase-1 gx for t=0
    float gxp0 = __ldcg(&g_gx[(size_t)e1b0 * N3_ + goff + c1 + e1c0]);
    float gxp1 = __ldcg(&g_gx[(size_t)e1b1 * N3_ + goff + c1 + e1c1]);

    unsigned tgt = 0;

    for (int t = 0; t < S_; t++) {
        // ================= phase 1: z and r =================
        float hown0 = 0.f, hown1 = 0.f;
        if (gate) {
            hown0 = __ldcg(&g_h[e1b0 * H_ + c1 + e1c0]);
            hown1 = __ldcg(&g_h[e1b1 * H_ + c1 + e1c1]);
        }
        stage_one(g_hf, s_t0);
        // prefetch phase-2 constants (constant buffer / own-written h)
        float gxg = __ldcg(&g_gx[((size_t)t * B_ + e2b) * N3_ + 2 * H_ + j2]);
        float hv = g_h[e2b * H_ + j2];
        __syncthreads();

        float acc[2][2][4];
#pragma unroll
        for (int mt = 0; mt < 2; mt++)
#pragma unroll
            for (int nt = 0; nt < 2; nt++)
#pragma unroll
                for (int i = 0; i < 4; i++) acc[mt][nt][i] = 0.f;

#pragma unroll
        for (int ks = 0; ks < 8; ks++) {
            const int kw = warp * 64 + ks * 8 + tg;
            uint32_t ah[2][4];
#pragma unroll
            for (int mt = 0; mt < 2; mt++) {
                const uint32_t* b0 = s_t0 + (mt * 16 + g) * SW_PW;
                const uint32_t* b1 = b0 + 8 * SW_PW;
                ah[mt][0] = b0[kw];
                ah[mt][1] = b1[kw];
                ah[mt][2] = b0[kw + 4];
                ah[mt][3] = b1[kw + 4];
            }
#pragma unroll
            for (int mt = 0; mt < 2; mt++)
#pragma unroll
                for (int nt = 0; nt < 2; nt++)
                    mma_f16(acc[mt][nt], ah[mt], w1f[nt][ks]);
        }

        // cross-warp K reduction
#pragma unroll
        for (int mt = 0; mt < 2; mt++)
#pragma unroll
            for (int nt = 0; nt < 2; nt++)
#pragma unroll
                for (int i = 0; i < 4; i++) {
                    int row = mt * 16 + g + (i >> 1) * 8;
                    int col = nt * 8 + tg * 2 + (i & 1);
                    red[(warp * 32 + row) * RED_STRIDE + col] = acc[mt][nt][i];
                }
        __syncthreads();

        {
            float v0 = 0.f, v1 = 0.f;
#pragma unroll
            for (int w = 0; w < 8; w++) {
                v0 += red[(w * 32 + e1b0) * RED_STRIDE + e1c0];
                v1 += red[(w * 32 + e1b1) * RED_STRIDE + e1c1];
            }
            float s0 = sigmoidf_(v0 + gxp0);
            float s1 = sigmoidf_(v1 + gxp1);
            if (gate == 0) {
                g_z[e1b0 * H_ + c1 + e1c0] = s0;
                g_z[e1b1 * H_ + c1 + e1c1] = s1;
            } else {
                g_rhf[e1b0 * H_ + c1 + e1c0] =
                    __half_as_ushort(__float2half(s0 * hown0));
                g_rhf[e1b1 * H_ + c1 + e1c1] =
                    __half_as_ushort(__float2half(s1 * hown1));
            }
        }

        tgt++;
        grid_sync_tree(tgt, grp);

        // ================= phase 2: g and h update =================
        float zv = __ldcg(&g_z[e2b * H_ + j2]);   // safe post-barrier
        stage_one(g_rhf, s_t0);
        __syncthreads();

        float acc2[2][4];
#pragma unroll
        for (int mt = 0; mt < 2; mt++)
#pragma unroll
            for (int i = 0; i < 4; i++) acc2[mt][i] = 0.f;

#pragma unroll
        for (int ks = 0; ks < 8; ks++) {
            const int kw = warp * 64 + ks * 8 + tg;
            uint32_t ah[2][4];
#pragma unroll
            for (int mt = 0; mt < 2; mt++) {
                const uint32_t* b0 = s_t0 + (mt * 16 + g) * SW_PW;
                const uint32_t* b1 = b0 + 8 * SW_PW;
                ah[mt][0] = b0[kw];
                ah[mt][1] = b1[kw];
                ah[mt][2] = b0[kw + 4];
                ah[mt][3] = b1[kw + 4];
            }
#pragma unroll
            for (int mt = 0; mt < 2; mt++)
                mma_f16(acc2[mt], ah[mt], w2f[ks]);
        }

#pragma unroll
        for (int mt = 0; mt < 2; mt++)
#pragma unroll
            for (int i = 0; i < 4; i++) {
                int row = mt * 16 + g + (i >> 1) * 8;
                int col = tg * 2 + (i & 1);
                red[(warp * 32 + row) * RED_STRIDE + col] = acc2[mt][i];
            }
        __syncthreads();

        {
            float v = 0.f;
#pragma unroll
            for (int w = 0; w < 8; w++) v += red[(w * 32 + e2b) * RED_STRIDE + e2c];
            size_t row = (size_t)t * B_ + e2b;
            float gv = tanhf(v + gxg);
            float hn = fmaf(zv, gv - hv, hv);

            g_h[e2b * H_ + j2] = hn;
            g_hf[e2b * H_ + j2] = __half_as_ushort(__float2half(hn));
            unsigned short bh, bl;
            split1(hn, bh, bl);
            g_seqh[row * H_ + j2] = bh;
            g_seql[row * H_ + j2] = bl;
            if (hid_out && t == S_ - 1)
                hid_out[((size_t)e2b * L_ + layer) * H_ + j2] = hn;
        }

        // prefetch next step's phase-1 gx (constant data)
        if (t + 1 < S_) {
            gxp0 = __ldcg(&g_gx[((size_t)(t + 1) * B_ + e1b0) * N3_ + goff + c1 + e1c0]);
            gxp1 = __ldcg(&g_gx[((size_t)(t + 1) * B_ + e1b1) * N3_ + goff + c1 + e1c1]);
        }

        tgt++;
        grid_sync_tree(tgt, grp);
    }
}

// ---------------------------------------------------------------------------
// Launch
// ---------------------------------------------------------------------------
extern "C" void kernel_launch(void* const* d_in, const int* in_sizes, int n_in,
                              void* d_out, int out_size) {
    (void)in_sizes; (void)n_in;
    const float* x   = (const float*)d_in[0];
    const float* h0  = (const float*)d_in[1];
    const float* Wzx = (const float*)d_in[2];
    const float* bz  = (const float*)d_in[3];
    const float* Wzh = (const float*)d_in[4];
    const float* Wrx = (const float*)d_in[5];
    const float* br  = (const float*)d_in[6];
    const float* Wrh = (const float*)d_in[7];
    const float* Wgx = (const float*)d_in[8];
    const float* bg  = (const float*)d_in[9];
    const float* Wgh = (const float*)d_in[10];
    const float* Wo  = (const float*)d_in[11];
    const float* bo  = (const float*)d_in[12];

    float* out = (float*)d_out;
    float* y_out = out;
    const long long need = (long long)B_ * S_ * OUT_ + (long long)B_ * L_ * H_;
    float* hid_out = ((long long)out_size >= need) ? out + (size_t)B_ * S_ * OUT_
                                                   : nullptr;

    cudaFuncSetAttribute(k_gru_recur,
        cudaFuncAttributeMaxDynamicSharedMemorySize, SMEMR);

    // operand prep
    k_transpose_x<<<M_, 256>>>(x);
    const int wbig4 = (L_ * H_ * IN_) / 4;   // 524288
    const int wout4 = (OUT_ * H_) / 4;       // 262144
    k_split<<<wbig4 / 256, 256>>>(Wzx, 0, wbig4);
    k_split<<<wbig4 / 256, 256>>>(Wrx, 1, wbig4);
    k_split<<<wbig4 / 256, 256>>>(Wgx, 2, wbig4);
    k_split<<<wout4 / 256, 256>>>(Wo, 3, wout4);
    k_split16<<<wbig4 / 256, 256>>>(Wzh, 0, wbig4);
    k_split16<<<wbig4 / 256, 256>>>(Wrh, 1, wbig4);
    k_split16<<<wbig4 / 256, 256>>>(Wgh, 2, wbig4);

    dim3 tgrid(1024 / 64, M_ / 128);   // (16, 128)

    for (int layer = 0; layer < L_; layer++) {
        k_prep<<<(B_ * H_) / 256, 256>>>(h0, layer);

        const int woff = layer * H_ * IN_;
        k_hmma<<<tgrid, 256>>>(layer, 0, woff, bz + (size_t)layer * H_,
                               nullptr, N3_, 0, 0);
        k_hmma<<<tgrid, 256>>>(layer, 1, woff, br + (size_t)layer * H_,
                               nullptr, N3_, H_, 0);
        k_hmma<<<tgrid, 256>>>(layer, 2, woff, bg + (size_t)layer * H_,
                               nullptr, N3_, 2 * H_, 0);

        k_gru_recur<<<NBLK, 256, SMEMR>>>(layer, hid_out);
    }

    // output projection
    k_hmma<<<tgrid, 256>>>(1, 3, 0, bo, y_out, OUT_, 0, 1);
}

// round 13
// speedup vs baseline: 1.1415x; 1.1415x over previous
#include <cuda_runtime.h>
#include <cuda_bf16.h>
#include <cuda_fp16.h>
#include <math.h>
#include <stdint.h>

// ---------------------------------------------------------------------------
// MultilayerGRU: B=32, S=512, I=H=O=1024, L=2
// R13: R11 base (flat barrier, proven 10.15ms) + column-aligned ownership:
//      block bx owns cols [8bx, 8bx+8) for z, r AND g. Phase 1 computes z+r
//      (z stays in registers), phase 2 computes g + update. Warp-local tile
//      staging (each warp stages only its own k-slice; __syncwarp only).
//      Numerics identical to R11 (fp16 1-term, fp32 master h).
// ---------------------------------------------------------------------------

#define B_  32
#define S_  512
#define IN_ 1024
#define H_  1024
#define OUT_ 1024
#define L_  2
#define M_  (B_ * S_)      /* 16384 */
#define N3_ (3 * H_)       /* 3072  */
#define NBLK 128

// ---------------- device scratch ------------------------------------------
__device__ float g_gx[(size_t)M_ * N3_];   // x-projections for current layer
__device__ float g_h[B_ * H_];             // fp32 master hidden state

__device__ __align__(16) unsigned short g_hf[B_ * H_];    // h fp16
__device__ __align__(16) unsigned short g_rhf[B_ * H_];   // r*h fp16

// bf16 hi/lo operand buffers (GEMM path)
__device__ __align__(16) unsigned short g_xh[(size_t)M_ * IN_],  g_xl[(size_t)M_ * IN_];
__device__ __align__(16) unsigned short g_seqh[(size_t)M_ * H_], g_seql[(size_t)M_ * H_];
__device__ __align__(16) unsigned short g_wzxh[(size_t)L_ * H_ * IN_], g_wzxl[(size_t)L_ * H_ * IN_];
__device__ __align__(16) unsigned short g_wrxh[(size_t)L_ * H_ * IN_], g_wrxl[(size_t)L_ * H_ * IN_];
__device__ __align__(16) unsigned short g_wgxh[(size_t)L_ * H_ * IN_], g_wgxl[(size_t)L_ * H_ * IN_];
__device__ __align__(16) unsigned short g_woh[(size_t)OUT_ * H_],      g_wol[(size_t)OUT_ * H_];

// fp16 recurrence weights
__device__ __align__(16) unsigned short g_wzhf[(size_t)L_ * H_ * H_];
__device__ __align__(16) unsigned short g_wrhf[(size_t)L_ * H_ * H_];
__device__ __align__(16) unsigned short g_wghf[(size_t)L_ * H_ * H_];

// flat grid barrier (generation-based; replay-safe via k_prep reset)
__device__ unsigned g_bar_count;
__device__ volatile unsigned g_bar_gen;

__device__ __forceinline__ void grid_sync() {
    __syncthreads();
    if (threadIdx.x == 0) {
        __threadfence();
        unsigned gen = g_bar_gen;
        if (atomicAdd(&g_bar_count, 1u) == NBLK - 1u) {
            g_bar_count = 0;
            __threadfence();
            g_bar_gen = gen + 1u;
        } else {
            while (g_bar_gen == gen) { }
        }
    }
    __syncthreads();
}

// ---------------------------------------------------------------------------
__device__ __forceinline__ void split1(float v, unsigned short& h, unsigned short& l) {
    __nv_bfloat16 hb = __float2bfloat16(v);
    float r = v - __bfloat162float(hb);
    __nv_bfloat16 lb = __float2bfloat16(r);
    h = __bfloat16_as_ushort(hb);
    l = __bfloat16_as_ushort(lb);
}

// mma.sync m16n8k16 row.col, bf16 and fp16 flavors
__device__ __forceinline__ void mma_bf16(float* c, const uint32_t* a, const uint32_t* b) {
    asm volatile(
        "mma.sync.aligned.m16n8k16.row.col.f32.bf16.bf16.f32 "
        "{%0,%1,%2,%3}, {%4,%5,%6,%7}, {%8,%9}, {%0,%1,%2,%3};"
        : "+f"(c[0]), "+f"(c[1]), "+f"(c[2]), "+f"(c[3])
        : "r"(a[0]), "r"(a[1]), "r"(a[2]), "r"(a[3]), "r"(b[0]), "r"(b[1]));
}

__device__ __forceinline__ void mma_f16(float* c, const uint32_t* a, const uint32_t* b) {
    asm volatile(
        "mma.sync.aligned.m16n8k16.row.col.f32.f16.f16.f32 "
        "{%0,%1,%2,%3}, {%4,%5,%6,%7}, {%8,%9}, {%0,%1,%2,%3};"
        : "+f"(c[0]), "+f"(c[1]), "+f"(c[2]), "+f"(c[3])
        : "r"(a[0]), "r"(a[1]), "r"(a[2]), "r"(a[3]), "r"(b[0]), "r"(b[1]));
}

__device__ __forceinline__ float sigmoidf_(float x) {
    return 1.f / (1.f + expf(-x));
}

// ---------------------------------------------------------------------------
// x[b][t][i] -> hi/lo bf16 [t*B+b][i]
// ---------------------------------------------------------------------------
__global__ void k_transpose_x(const float* __restrict__ x) {
    int row = blockIdx.x;
    int t = row / B_;
    int b = row % B_;
    const float4* src = (const float4*)(x + ((size_t)b * S_ + t) * IN_);
    ushort4* dh = (ushort4*)(g_xh + (size_t)row * IN_);
    ushort4* dl = (ushort4*)(g_xl + (size_t)row * IN_);
    for (int i = threadIdx.x; i < IN_ / 4; i += blockDim.x) {
        float4 v = src[i];
        ushort4 h, l;
        split1(v.x, h.x, l.x);
        split1(v.y, h.y, l.y);
        split1(v.z, h.z, l.z);
        split1(v.w, h.w, l.w);
        dh[i] = h;
        dl[i] = l;
    }
}

// ---------------------------------------------------------------------------
// weight splits
// ---------------------------------------------------------------------------
__global__ void k_split(const float* __restrict__ src, int wsel, int n4) {
    int i = blockIdx.x * blockDim.x + threadIdx.x;
    if (i >= n4) return;
    unsigned short* hi;
    unsigned short* lo;
    switch (wsel) {
        case 0: hi = g_wzxh; lo = g_wzxl; break;
        case 1: hi = g_wrxh; lo = g_wrxl; break;
        case 2: hi = g_wgxh; lo = g_wgxl; break;
        default: hi = g_woh;  lo = g_wol; break;
    }
    float4 v = ((const float4*)src)[i];
    ushort4 h, l;
    split1(v.x, h.x, l.x);
    split1(v.y, h.y, l.y);
    split1(v.z, h.z, l.z);
    split1(v.w, h.w, l.w);
    ((ushort4*)hi)[i] = h;
    ((ushort4*)lo)[i] = l;
}

__global__ void k_split16(const float* __restrict__ src, int wsel, int n4) {
    int i = blockIdx.x * blockDim.x + threadIdx.x;
    if (i >= n4) return;
    float4 v = ((const float4*)src)[i];
    unsigned short* hi = (wsel == 0) ? g_wzhf : (wsel == 1) ? g_wrhf : g_wghf;
    ushort4 h;
    h.x = __half_as_ushort(__float2half(v.x));
    h.y = __half_as_ushort(__float2half(v.y));
    h.z = __half_as_ushort(__float2half(v.z));
    h.w = __half_as_ushort(__float2half(v.w));
    ((ushort4*)hi)[i] = h;
}

// ---------------------------------------------------------------------------
// k_prep: g_h / g_hf from h0[b][layer][:]; reset barrier.
// ---------------------------------------------------------------------------
__global__ void k_prep(const float* __restrict__ h0, int layer) {
    int idx = blockIdx.x * blockDim.x + threadIdx.x;  // [0, B*H)
    if (idx == 0) { g_bar_count = 0; g_bar_gen = 0; }
    int b = idx / H_;
    int c = idx % H_;
    float v = h0[((size_t)b * L_ + layer) * H_ + c];
    g_h[idx] = v;
    g_hf[idx] = __half_as_ushort(__float2half(v));
}

// ---------------------------------------------------------------------------
// HMMA split-bf16 GEMM (unchanged, proven).
// ---------------------------------------------------------------------------
#define HMP 40

__global__ void __launch_bounds__(256) k_hmma(
    int asel, int wsel, int woff,
    const float* __restrict__ bias, float* __restrict__ Cout,
    int ldc, int col0, int permC)
{
    __shared__ __align__(16) unsigned short As_h[128 * HMP];
    __shared__ __align__(16) unsigned short As_l[128 * HMP];
    __shared__ __align__(16) unsigned short Bs_h[64 * HMP];
    __shared__ __align__(16) unsigned short Bs_l[64 * HMP];

    const int tid = threadIdx.x;
    const int m0 = blockIdx.y * 128, n0 = blockIdx.x * 64;

    const unsigned short* Ah = asel ? g_seqh : g_xh;
    const unsigned short* Al = asel ? g_seql : g_xl;
    const unsigned short* Wh;
    const unsigned short* Wl;
    switch (wsel) {
        case 0: Wh = g_wzxh; Wl = g_wzxl; break;
        case 1: Wh = g_wrxh; Wl = g_wrxl; break;
        case 2: Wh = g_wgxh; Wl = g_wgxl; break;
        default: Wh = g_woh; Wl = g_wol; break;
    }
    Wh += woff; Wl += woff;

    const int ar0 = (2 * tid) >> 2,     au0 = (2 * tid) & 3;
    const int ar1 = (2 * tid + 1) >> 2, au1 = (2 * tid + 1) & 3;
    const int br  = tid >> 2,           bu  = tid & 3;

    const int warp = tid >> 5, lane = tid & 31;
    const int g = lane >> 2, tg = lane & 3;
    const int wm = warp >> 1, wn = warp & 1;

    float acc[2][4][4];
#pragma unroll
    for (int mt = 0; mt < 2; mt++)
#pragma unroll
        for (int nt = 0; nt < 4; nt++)
#pragma unroll
            for (int i = 0; i < 4; i++) acc[mt][nt][i] = 0.f;

    const uint32_t* Awh = (const uint32_t*)As_h;
    const uint32_t* Awl = (const uint32_t*)As_l;
    const uint32_t* Bwh = (const uint32_t*)Bs_h;
    const uint32_t* Bwl = (const uint32_t*)Bs_l;

    uint4 vah0, vah1, val0, val1, vbh, vbl;
    vah0 = *(const uint4*)(Ah + (size_t)(m0 + ar0) * 1024 + au0 * 8);
    vah1 = *(const uint4*)(Ah + (size_t)(m0 + ar1) * 1024 + au1 * 8);
    val0 = *(const uint4*)(Al + (size_t)(m0 + ar0) * 1024 + au0 * 8);
    val1 = *(const uint4*)(Al + (size_t)(m0 + ar1) * 1024 + au1 * 8);
    vbh  = *(const uint4*)(Wh + (size_t)(n0 + br) * 1024 + bu * 8);
    vbl  = *(const uint4*)(Wl + (size_t)(n0 + br) * 1024 + bu * 8);

    for (int kc = 0; kc < 32; kc++) {
        __syncthreads();
        *(uint4*)(As_h + ar0 * HMP + au0 * 8) = vah0;
        *(uint4*)(As_h + ar1 * HMP + au1 * 8) = vah1;
        *(uint4*)(As_l + ar0 * HMP + au0 * 8) = val0;
        *(uint4*)(As_l + ar1 * HMP + au1 * 8) = val1;
        *(uint4*)(Bs_h + br * HMP + bu * 8) = vbh;
        *(uint4*)(Bs_l + br * HMP + bu * 8) = vbl;
        if (kc + 1 < 32) {
            int ko = (kc + 1) * 32;
            vah0 = *(const uint4*)(Ah + (size_t)(m0 + ar0) * 1024 + ko + au0 * 8);
            vah1 = *(const uint4*)(Ah + (size_t)(m0 + ar1) * 1024 + ko + au1 * 8);
            val0 = *(const uint4*)(Al + (size_t)(m0 + ar0) * 1024 + ko + au0 * 8);
            val1 = *(const uint4*)(Al + (size_t)(m0 + ar1) * 1024 + ko + au1 * 8);
            vbh  = *(const uint4*)(Wh + (size_t)(n0 + br) * 1024 + ko + bu * 8);
            vbl  = *(const uint4*)(Wl + (size_t)(n0 + br) * 1024 + ko + bu * 8);
        }
        __syncthreads();

#pragma unroll
        for (int ks = 0; ks < 2; ks++) {
            const int kw = ks * 8 + tg;
            uint32_t ahf[2][4], alf[2][4];
#pragma unroll
            for (int mt = 0; mt < 2; mt++) {
                int rb = (wm * 32 + mt * 16 + g) * 20 + kw;
                ahf[mt][0] = Awh[rb];
                ahf[mt][1] = Awh[rb + 160];
                ahf[mt][2] = Awh[rb + 4];
                ahf[mt][3] = Awh[rb + 164];
                alf[mt][0] = Awl[rb];
                alf[mt][1] = Awl[rb + 160];
                alf[mt][2] = Awl[rb + 4];
                alf[mt][3] = Awl[rb + 164];
            }
            uint32_t bhf[4][2], blf[4][2];
#pragma unroll
            for (int nt = 0; nt < 4; nt++) {
                int rb = (wn * 32 + nt * 8 + g) * 20 + kw;
                bhf[nt][0] = Bwh[rb];
                bhf[nt][1] = Bwh[rb + 4];
                blf[nt][0] = Bwl[rb];
                blf[nt][1] = Bwl[rb + 4];
            }
#pragma unroll
            for (int mt = 0; mt < 2; mt++)
#pragma unroll
                for (int nt = 0; nt < 4; nt++) {
                    mma_bf16(acc[mt][nt], ahf[mt], bhf[nt]);
                    mma_bf16(acc[mt][nt], ahf[mt], blf[nt]);
                    mma_bf16(acc[mt][nt], alf[mt], bhf[nt]);
                }
        }
    }

#pragma unroll
    for (int mt = 0; mt < 2; mt++) {
#pragma unroll
        for (int nt = 0; nt < 4; nt++) {
            int mrow = m0 + wm * 32 + mt * 16 + g;
            int ncol = n0 + wn * 32 + nt * 8 + tg * 2;
            float bx = bias[ncol], by = bias[ncol + 1];
#pragma unroll
            for (int half = 0; half < 2; half++) {
                int m = mrow + half * 8;
                float2 o;
                o.x = acc[mt][nt][half * 2 + 0] + bx;
                o.y = acc[mt][nt][half * 2 + 1] + by;
                float* dst;
                if (permC) {
                    int b = m & (B_ - 1);
                    int t = m >> 5;
                    dst = Cout + ((size_t)b * S_ + t) * ldc + ncol;
                } else {
                    dst = g_gx + (size_t)m * ldc + col0 + ncol;
                }
                *(float2*)dst = o;
            }
        }
    }
}

// ---------------------------------------------------------------------------
// fp16 tensor-core recurrence, column-aligned ownership.
//   Block bx owns cols [8bx, 8bx+8). Phase 1: z+r (2 n-tiles), z kept in
//   registers. Phase 2: g (1 n-tile) + h update.
//   Warp-local staging: warp w stages rows 0..31 x uint4-cols [16w,16w+16).
// ---------------------------------------------------------------------------
#define SW_PW 516
#define TILE_B (32 * SW_PW * 4)            /* 66048 bytes tile buffer */
#define RED_STRIDE 18
#define RED_B (8 * 32 * RED_STRIDE * 4)    /* 18432 */
#define SMEMR (TILE_B + RED_B)             /* 84480 */

// warp-local stage: warp stages its own k-slice; only __syncwarp needed after.
__device__ __forceinline__ void stage_warp(
    const unsigned short* __restrict__ gsrc, uint32_t* __restrict__ s,
    int warp, int lane)
{
    const int colq = warp * 16 + (lane & 15);   // uint4 column within row
    const int rb = lane >> 4;                    // row parity
#pragma unroll
    for (int half = 0; half < 2; half++) {
        uint4 v[8];
#pragma unroll
        for (int it = 0; it < 8; it++) {
            int row = (half * 8 + it) * 2 + rb;
            v[it] = __ldcg((const uint4*)(gsrc + (size_t)row * H_) + colq);
        }
#pragma unroll
        for (int it = 0; it < 8; it++) {
            int row = (half * 8 + it) * 2 + rb;
            *(uint4*)(s + row * SW_PW + colq * 4) = v[it];
        }
    }
}

__global__ void __launch_bounds__(256, 1) k_gru_recur(
    int layer, float* __restrict__ hid_out)
{
    extern __shared__ char smem[];
    uint32_t* s_t0 = (uint32_t*)smem;                    // tile [32][516]
    float*    red  = (float*)(smem + TILE_B);            // [8][32][18]

    const int tid = threadIdx.x;
    const int warp = tid >> 5, lane = tid & 31;
    const int g = lane >> 2, tg = lane & 3;

    // ---- ownership: 8 columns for z, r and g ----
    const int c0 = blockIdx.x * 8;
    const size_t lw = (size_t)layer * H_ * H_;

    // ---- resident weight fragments (single fp16) ----
    uint32_t w1f[2][8][2];   // nt0 = Wzh rows c0+g, nt1 = Wrh rows c0+g
    uint32_t w2f[8][2];      // Wgh rows c0+g
    {
#pragma unroll
        for (int ks = 0; ks < 8; ks++) {
            int kw = warp * 64 + ks * 8 + tg;
            const uint32_t* wz = (const uint32_t*)(g_wzhf + lw + (size_t)(c0 + g) * H_);
            const uint32_t* wr = (const uint32_t*)(g_wrhf + lw + (size_t)(c0 + g) * H_);
            const uint32_t* wg = (const uint32_t*)(g_wghf + lw + (size_t)(c0 + g) * H_);
            w1f[0][ks][0] = wz[kw];
            w1f[0][ks][1] = wz[kw + 4];
            w1f[1][ks][0] = wr[kw];
            w1f[1][ks][1] = wr[kw + 4];
            w2f[ks][0] = wg[kw];
            w2f[ks][1] = wg[kw + 4];
        }
    }

    // epilogue map: thread -> (batch b, own col c)
    const int eb = tid >> 3, ec = tid & 7;
    const int j = c0 + ec;

    // prefetch phase-1 gx for t=0
    float gxz = __ldcg(&g_gx[(size_t)eb * N3_ + j]);
    float gxr = __ldcg(&g_gx[(size_t)eb * N3_ + H_ + j]);

    for (int t = 0; t < S_; t++) {
        const size_t row = (size_t)t * B_ + eb;

        // own h (serves r*h input AND update operand) + phase-2 gx
        float hv  = __ldcg(&g_h[eb * H_ + j]);
        float gxg = __ldcg(&g_gx[row * N3_ + 2 * H_ + j]);

        // ================= phase 1: z and r =================
        stage_warp(g_hf, s_t0, warp, lane);
        __syncwarp();

        float acc[2][2][4];
#pragma unroll
        for (int mt = 0; mt < 2; mt++)
#pragma unroll
            for (int nt = 0; nt < 2; nt++)
#pragma unroll
                for (int i = 0; i < 4; i++) acc[mt][nt][i] = 0.f;

#pragma unroll
        for (int ks = 0; ks < 8; ks++) {
            const int kw = warp * 64 + ks * 8 + tg;
            uint32_t ah[2][4];
#pragma unroll
            for (int mt = 0; mt < 2; mt++) {
                const uint32_t* b0 = s_t0 + (mt * 16 + g) * SW_PW;
                const uint32_t* b1 = b0 + 8 * SW_PW;
                ah[mt][0] = b0[kw];
                ah[mt][1] = b1[kw];
                ah[mt][2] = b0[kw + 4];
                ah[mt][3] = b1[kw + 4];
            }
#pragma unroll
            for (int mt = 0; mt < 2; mt++)
#pragma unroll
                for (int nt = 0; nt < 2; nt++)
                    mma_f16(acc[mt][nt], ah[mt], w1f[nt][ks]);
        }

        // cross-warp K reduction: cols 0-7 = z, 8-15 = r
#pragma unroll
        for (int mt = 0; mt < 2; mt++)
#pragma unroll
            for (int nt = 0; nt < 2; nt++)
#pragma unroll
                for (int i = 0; i < 4; i++) {
                    int brow = mt * 16 + g + (i >> 1) * 8;
                    int col = nt * 8 + tg * 2 + (i & 1);
                    red[(warp * 32 + brow) * RED_STRIDE + col] = acc[mt][nt][i];
                }
        __syncthreads();

        float zreg;
        {
            float vz = 0.f, vr = 0.f;
#pragma unroll
            for (int w = 0; w < 8; w++) {
                vz += red[(w * 32 + eb) * RED_STRIDE + ec];
                vr += red[(w * 32 + eb) * RED_STRIDE + 8 + ec];
            }
            zreg = sigmoidf_(vz + gxz);
            float r = sigmoidf_(vr + gxr);
            g_rhf[eb * H_ + j] = __half_as_ushort(__float2half(r * hv));
        }

        grid_sync();

        // ================= phase 2: g and h update =================
        stage_warp(g_rhf, s_t0, warp, lane);
        __syncwarp();

        float acc2[2][4];
#pragma unroll
        for (int mt = 0; mt < 2; mt++)
#pragma unroll
            for (int i = 0; i < 4; i++) acc2[mt][i] = 0.f;

#pragma unroll
        for (int ks = 0; ks < 8; ks++) {
            const int kw = warp * 64 + ks * 8 + tg;
            uint32_t ah[2][4];
#pragma unroll
            for (int mt = 0; mt < 2; mt++) {
                const uint32_t* b0 = s_t0 + (mt * 16 + g) * SW_PW;
                const uint32_t* b1 = b0 + 8 * SW_PW;
                ah[mt][0] = b0[kw];
                ah[mt][1] = b1[kw];
                ah[mt][2] = b0[kw + 4];
                ah[mt][3] = b1[kw + 4];
            }
#pragma unroll
            for (int mt = 0; mt < 2; mt++)
                mma_f16(acc2[mt], ah[mt], w2f[ks]);
        }

#pragma unroll
        for (int mt = 0; mt < 2; mt++)
#pragma unroll
            for (int i = 0; i < 4; i++) {
                int brow = mt * 16 + g + (i >> 1) * 8;
                int col = tg * 2 + (i & 1);
                red[(warp * 32 + brow) * RED_STRIDE + col] = acc2[mt][i];
            }
        __syncthreads();

        {
            float v = 0.f;
#pragma unroll
            for (int w = 0; w < 8; w++) v += red[(w * 32 + eb) * RED_STRIDE + ec];
            float gv = tanhf(v + gxg);
            float hn = fmaf(zreg, gv - hv, hv);

            g_h[eb * H_ + j] = hn;
            g_hf[eb * H_ + j] = __half_as_ushort(__float2half(hn));
            unsigned short bh, bl;
            split1(hn, bh, bl);
            g_seqh[row * H_ + j] = bh;
            g_seql[row * H_ + j] = bl;
            if (hid_out && t == S_ - 1)
                hid_out[((size_t)eb * L_ + layer) * H_ + j] = hn;
        }

        // prefetch next step's phase-1 gx (constant data)
        if (t + 1 < S_) {
            gxz = __ldcg(&g_gx[((size_t)(t + 1) * B_ + eb) * N3_ + j]);
            gxr = __ldcg(&g_gx[((size_t)(t + 1) * B_ + eb) * N3_ + H_ + j]);
        }

        grid_sync();
    }
}

// ---------------------------------------------------------------------------
// Launch
// ---------------------------------------------------------------------------
extern "C" void kernel_launch(void* const* d_in, const int* in_sizes, int n_in,
                              void* d_out, int out_size) {
    (void)in_sizes; (void)n_in;
    const float* x   = (const float*)d_in[0];
    const float* h0  = (const float*)d_in[1];
    const float* Wzx = (const float*)d_in[2];
    const float* bz  = (const float*)d_in[3];
    const float* Wzh = (const float*)d_in[4];
    const float* Wrx = (const float*)d_in[5];
    const float* br  = (const float*)d_in[6];
    const float* Wrh = (const float*)d_in[7];
    const float* Wgx = (const float*)d_in[8];
    const float* bg  = (const float*)d_in[9];
    const float* Wgh = (const float*)d_in[10];
    const float* Wo  = (const float*)d_in[11];
    const float* bo  = (const float*)d_in[12];

    float* out = (float*)d_out;
    float* y_out = out;
    const long long need = (long long)B_ * S_ * OUT_ + (long long)B_ * L_ * H_;
    float* hid_out = ((long long)out_size >= need) ? out + (size_t)B_ * S_ * OUT_
                                                   : nullptr;

    cudaFuncSetAttribute(k_gru_recur,
        cudaFuncAttributeMaxDynamicSharedMemorySize, SMEMR);

    // operand prep
    k_transpose_x<<<M_, 256>>>(x);
    const int wbig4 = (L_ * H_ * IN_) / 4;   // 524288
    const int wout4 = (OUT_ * H_) / 4;       // 262144
    k_split<<<wbig4 / 256, 256>>>(Wzx, 0, wbig4);
    k_split<<<wbig4 / 256, 256>>>(Wrx, 1, wbig4);
    k_split<<<wbig4 / 256, 256>>>(Wgx, 2, wbig4);
    k_split<<<wout4 / 256, 256>>>(Wo, 3, wout4);
    k_split16<<<wbig4 / 256, 256>>>(Wzh, 0, wbig4);
    k_split16<<<wbig4 / 256, 256>>>(Wrh, 1, wbig4);
    k_split16<<<wbig4 / 256, 256>>>(Wgh, 2, wbig4);

    dim3 tgrid(1024 / 64, M_ / 128);   // (16, 128)

    for (int layer = 0; layer < L_; layer++) {
        k_prep<<<(B_ * H_) / 256, 256>>>(h0, layer);

        const int woff = layer * H_ * IN_;
        k_hmma<<<tgrid, 256>>>(layer, 0, woff, bz + (size_t)layer * H_,
                               nullptr, N3_, 0, 0);
        k_hmma<<<tgrid, 256>>>(layer, 1, woff, br + (size_t)layer * H_,
                               nullptr, N3_, H_, 0);
        k_hmma<<<tgrid, 256>>>(layer, 2, woff, bg + (size_t)layer * H_,
                               nullptr, N3_, 2 * H_, 0);

        k_gru_recur<<<NBLK, 256, SMEMR>>>(layer, hid_out);
    }

    // output projection
    k_hmma<<<tgrid, 256>>>(1, 3, 0, bo, y_out, OUT_, 0, 1);
}

// round 14
// speedup vs baseline: 1.5595x; 1.3662x over previous
#include <cuda_runtime.h>
#include <cuda_bf16.h>
#include <cuda_fp16.h>
#include <math.h>
#include <stdint.h>

// ---------------------------------------------------------------------------
// MultilayerGRU: B=32, S=512, I=H=O=1024, L=2
// R14: LAYER WAVEFRONT. One persistent kernel runs layer1 step k and layer2
//      step k-1 concurrently (513 super-steps, 2 barriers each) instead of
//      1024 steps — halves the barrier/latency-bound serial overhead.
//      Layer2 x-projections computed on-the-fly (fp16 MMA, weights in smem),
//      deleting 3 big GEMMs and all layer-1 seq stores. h1/h2 fp32 masters
//      live in per-thread registers. Numerics: fp16 1-term matvecs (proven),
//      layer2 gate inputs now fp16 as well.
// ---------------------------------------------------------------------------

#define B_  32
#define S_  512
#define IN_ 1024
#define H_  1024
#define OUT_ 1024
#define L_  2
#define M_  (B_ * S_)      /* 16384 */
#define N3_ (3 * H_)       /* 3072  */
#define NBLK 128

// ---------------- device scratch ------------------------------------------
__device__ float g_gx[(size_t)M_ * N3_];   // layer-1 x-projections

__device__ __align__(16) unsigned short g_h1f[B_ * H_];   // h1 fp16
__device__ __align__(16) unsigned short g_h2f[B_ * H_];   // h2 fp16
__device__ __align__(16) unsigned short g_rh1f[B_ * H_];  // r1*h1 fp16
__device__ __align__(16) unsigned short g_rh2f[B_ * H_];  // r2*h2 fp16

// bf16 hi/lo operand buffers (GEMM path)
__device__ __align__(16) unsigned short g_xh[(size_t)M_ * IN_],  g_xl[(size_t)M_ * IN_];
__device__ __align__(16) unsigned short g_seqh[(size_t)M_ * H_], g_seql[(size_t)M_ * H_];
__device__ __align__(16) unsigned short g_wzxh[(size_t)H_ * IN_], g_wzxl[(size_t)H_ * IN_];
__device__ __align__(16) unsigned short g_wrxh[(size_t)H_ * IN_], g_wrxl[(size_t)H_ * IN_];
__device__ __align__(16) unsigned short g_wgxh[(size_t)H_ * IN_], g_wgxl[(size_t)H_ * IN_];
__device__ __align__(16) unsigned short g_woh[(size_t)OUT_ * H_], g_wol[(size_t)OUT_ * H_];

// fp16 recurrence weights (both layers) + layer2 x-weights
__device__ __align__(16) unsigned short g_wzhf[(size_t)L_ * H_ * H_];
__device__ __align__(16) unsigned short g_wrhf[(size_t)L_ * H_ * H_];
__device__ __align__(16) unsigned short g_wghf[(size_t)L_ * H_ * H_];
__device__ __align__(16) unsigned short g_wzx2f[(size_t)H_ * H_];
__device__ __align__(16) unsigned short g_wrx2f[(size_t)H_ * H_];
__device__ __align__(16) unsigned short g_wgx2f[(size_t)H_ * H_];

// flat grid barrier (reset by k_prep)
__device__ unsigned g_bar_count;
__device__ volatile unsigned g_bar_gen;

__device__ __forceinline__ void grid_sync() {
    __syncthreads();
    if (threadIdx.x == 0) {
        __threadfence();
        unsigned gen = g_bar_gen;
        if (atomicAdd(&g_bar_count, 1u) == NBLK - 1u) {
            g_bar_count = 0;
            __threadfence();
            g_bar_gen = gen + 1u;
        } else {
            while (g_bar_gen == gen) { }
        }
    }
    __syncthreads();
}

// ---------------------------------------------------------------------------
__device__ __forceinline__ void split1(float v, unsigned short& h, unsigned short& l) {
    __nv_bfloat16 hb = __float2bfloat16(v);
    float r = v - __bfloat162float(hb);
    __nv_bfloat16 lb = __float2bfloat16(r);
    h = __bfloat16_as_ushort(hb);
    l = __bfloat16_as_ushort(lb);
}

__device__ __forceinline__ void mma_bf16(float* c, const uint32_t* a, const uint32_t* b) {
    asm volatile(
        "mma.sync.aligned.m16n8k16.row.col.f32.bf16.bf16.f32 "
        "{%0,%1,%2,%3}, {%4,%5,%6,%7}, {%8,%9}, {%0,%1,%2,%3};"
        : "+f"(c[0]), "+f"(c[1]), "+f"(c[2]), "+f"(c[3])
        : "r"(a[0]), "r"(a[1]), "r"(a[2]), "r"(a[3]), "r"(b[0]), "r"(b[1]));
}

__device__ __forceinline__ void mma_f16(float* c, const uint32_t* a, const uint32_t* b) {
    asm volatile(
        "mma.sync.aligned.m16n8k16.row.col.f32.f16.f16.f32 "
        "{%0,%1,%2,%3}, {%4,%5,%6,%7}, {%8,%9}, {%0,%1,%2,%3};"
        : "+f"(c[0]), "+f"(c[1]), "+f"(c[2]), "+f"(c[3])
        : "r"(a[0]), "r"(a[1]), "r"(a[2]), "r"(a[3]), "r"(b[0]), "r"(b[1]));
}

__device__ __forceinline__ float sigmoidf_(float x) {
    return 1.f / (1.f + expf(-x));
}

// ---------------------------------------------------------------------------
// x[b][t][i] -> hi/lo bf16 [t*B+b][i]
// ---------------------------------------------------------------------------
__global__ void k_transpose_x(const float* __restrict__ x) {
    int row = blockIdx.x;
    int t = row / B_;
    int b = row % B_;
    const float4* src = (const float4*)(x + ((size_t)b * S_ + t) * IN_);
    ushort4* dh = (ushort4*)(g_xh + (size_t)row * IN_);
    ushort4* dl = (ushort4*)(g_xl + (size_t)row * IN_);
    for (int i = threadIdx.x; i < IN_ / 4; i += blockDim.x) {
        float4 v = src[i];
        ushort4 h, l;
        split1(v.x, h.x, l.x);
        split1(v.y, h.y, l.y);
        split1(v.z, h.z, l.z);
        split1(v.w, h.w, l.w);
        dh[i] = h;
        dl[i] = l;
    }
}

// ---------------------------------------------------------------------------
// weight splits (bf16 hi/lo for GEMM; fp16 for recurrence/wavefront)
// ---------------------------------------------------------------------------
__global__ void k_split(const float* __restrict__ src, int wsel, int n4) {
    int i = blockIdx.x * blockDim.x + threadIdx.x;
    if (i >= n4) return;
    unsigned short* hi;
    unsigned short* lo;
    switch (wsel) {
        case 0: hi = g_wzxh; lo = g_wzxl; break;
        case 1: hi = g_wrxh; lo = g_wrxl; break;
        case 2: hi = g_wgxh; lo = g_wgxl; break;
        default: hi = g_woh;  lo = g_wol; break;
    }
    float4 v = ((const float4*)src)[i];
    ushort4 h, l;
    split1(v.x, h.x, l.x);
    split1(v.y, h.y, l.y);
    split1(v.z, h.z, l.z);
    split1(v.w, h.w, l.w);
    ((ushort4*)hi)[i] = h;
    ((ushort4*)lo)[i] = l;
}

__global__ void k_split16(const float* __restrict__ src, int wsel, int n4) {
    int i = blockIdx.x * blockDim.x + threadIdx.x;
    if (i >= n4) return;
    float4 v = ((const float4*)src)[i];
    unsigned short* hi;
    switch (wsel) {
        case 0: hi = g_wzhf;  break;
        case 1: hi = g_wrhf;  break;
        case 2: hi = g_wghf;  break;
        case 3: hi = g_wzx2f; break;
        case 4: hi = g_wrx2f; break;
        default: hi = g_wgx2f; break;
    }
    ushort4 h;
    h.x = __half_as_ushort(__float2half(v.x));
    h.y = __half_as_ushort(__float2half(v.y));
    h.z = __half_as_ushort(__float2half(v.z));
    h.w = __half_as_ushort(__float2half(v.w));
    ((ushort4*)hi)[i] = h;
}

// ---------------------------------------------------------------------------
// k_prep: fp16 h states from h0; reset barrier.
// ---------------------------------------------------------------------------
__global__ void k_prep(const float* __restrict__ h0) {
    int idx = blockIdx.x * blockDim.x + threadIdx.x;  // [0, B*H)
    if (idx == 0) { g_bar_count = 0; g_bar_gen = 0; }
    int b = idx / H_;
    int c = idx % H_;
    g_h1f[idx] = __half_as_ushort(__float2half(h0[((size_t)b * L_ + 0) * H_ + c]));
    g_h2f[idx] = __half_as_ushort(__float2half(h0[((size_t)b * L_ + 1) * H_ + c]));
}

// ---------------------------------------------------------------------------
// HMMA split-bf16 GEMM (proven).  asel: 0 = g_x(h/l), 1 = g_seq(h/l)
// ---------------------------------------------------------------------------
#define HMP 40

__global__ void __launch_bounds__(256) k_hmma(
    int asel, int wsel,
    const float* __restrict__ bias, float* __restrict__ Cout,
    int ldc, int col0, int permC)
{
    __shared__ __align__(16) unsigned short As_h[128 * HMP];
    __shared__ __align__(16) unsigned short As_l[128 * HMP];
    __shared__ __align__(16) unsigned short Bs_h[64 * HMP];
    __shared__ __align__(16) unsigned short Bs_l[64 * HMP];

    const int tid = threadIdx.x;
    const int m0 = blockIdx.y * 128, n0 = blockIdx.x * 64;

    const unsigned short* Ah = asel ? g_seqh : g_xh;
    const unsigned short* Al = asel ? g_seql : g_xl;
    const unsigned short* Wh;
    const unsigned short* Wl;
    switch (wsel) {
        case 0: Wh = g_wzxh; Wl = g_wzxl; break;
        case 1: Wh = g_wrxh; Wl = g_wrxl; break;
        case 2: Wh = g_wgxh; Wl = g_wgxl; break;
        default: Wh = g_woh; Wl = g_wol; break;
    }

    const int ar0 = (2 * tid) >> 2,     au0 = (2 * tid) & 3;
    const int ar1 = (2 * tid + 1) >> 2, au1 = (2 * tid + 1) & 3;
    const int br  = tid >> 2,           bu  = tid & 3;

    const int warp = tid >> 5, lane = tid & 31;
    const int g = lane >> 2, tg = lane & 3;
    const int wm = warp >> 1, wn = warp & 1;

    float acc[2][4][4];
#pragma unroll
    for (int mt = 0; mt < 2; mt++)
#pragma unroll
        for (int nt = 0; nt < 4; nt++)
#pragma unroll
            for (int i = 0; i < 4; i++) acc[mt][nt][i] = 0.f;

    const uint32_t* Awh = (const uint32_t*)As_h;
    const uint32_t* Awl = (const uint32_t*)As_l;
    const uint32_t* Bwh = (const uint32_t*)Bs_h;
    const uint32_t* Bwl = (const uint32_t*)Bs_l;

    uint4 vah0, vah1, val0, val1, vbh, vbl;
    vah0 = *(const uint4*)(Ah + (size_t)(m0 + ar0) * 1024 + au0 * 8);
    vah1 = *(const uint4*)(Ah + (size_t)(m0 + ar1) * 1024 + au1 * 8);
    val0 = *(const uint4*)(Al + (size_t)(m0 + ar0) * 1024 + au0 * 8);
    val1 = *(const uint4*)(Al + (size_t)(m0 + ar1) * 1024 + au1 * 8);
    vbh  = *(const uint4*)(Wh + (size_t)(n0 + br) * 1024 + bu * 8);
    vbl  = *(const uint4*)(Wl + (size_t)(n0 + br) * 1024 + bu * 8);

    for (int kc = 0; kc < 32; kc++) {
        __syncthreads();
        *(uint4*)(As_h + ar0 * HMP + au0 * 8) = vah0;
        *(uint4*)(As_h + ar1 * HMP + au1 * 8) = vah1;
        *(uint4*)(As_l + ar0 * HMP + au0 * 8) = val0;
        *(uint4*)(As_l + ar1 * HMP + au1 * 8) = val1;
        *(uint4*)(Bs_h + br * HMP + bu * 8) = vbh;
        *(uint4*)(Bs_l + br * HMP + bu * 8) = vbl;
        if (kc + 1 < 32) {
            int ko = (kc + 1) * 32;
            vah0 = *(const uint4*)(Ah + (size_t)(m0 + ar0) * 1024 + ko + au0 * 8);
            vah1 = *(const uint4*)(Ah + (size_t)(m0 + ar1) * 1024 + ko + au1 * 8);
            val0 = *(const uint4*)(Al + (size_t)(m0 + ar0) * 1024 + ko + au0 * 8);
            val1 = *(const uint4*)(Al + (size_t)(m0 + ar1) * 1024 + ko + au1 * 8);
            vbh  = *(const uint4*)(Wh + (size_t)(n0 + br) * 1024 + ko + bu * 8);
            vbl  = *(const uint4*)(Wl + (size_t)(n0 + br) * 1024 + ko + bu * 8);
        }
        __syncthreads();

#pragma unroll
        for (int ks = 0; ks < 2; ks++) {
            const int kw = ks * 8 + tg;
            uint32_t ahf[2][4], alf[2][4];
#pragma unroll
            for (int mt = 0; mt < 2; mt++) {
                int rb = (wm * 32 + mt * 16 + g) * 20 + kw;
                ahf[mt][0] = Awh[rb];
                ahf[mt][1] = Awh[rb + 160];
                ahf[mt][2] = Awh[rb + 4];
                ahf[mt][3] = Awh[rb + 164];
                alf[mt][0] = Awl[rb];
                alf[mt][1] = Awl[rb + 160];
                alf[mt][2] = Awl[rb + 4];
                alf[mt][3] = Awl[rb + 164];
            }
            uint32_t bhf[4][2], blf[4][2];
#pragma unroll
            for (int nt = 0; nt < 4; nt++) {
                int rb = (wn * 32 + nt * 8 + g) * 20 + kw;
                bhf[nt][0] = Bwh[rb];
                bhf[nt][1] = Bwh[rb + 4];
                blf[nt][0] = Bwl[rb];
                blf[nt][1] = Bwl[rb + 4];
            }
#pragma unroll
            for (int mt = 0; mt < 2; mt++)
#pragma unroll
                for (int nt = 0; nt < 4; nt++) {
                    mma_bf16(acc[mt][nt], ahf[mt], bhf[nt]);
                    mma_bf16(acc[mt][nt], ahf[mt], blf[nt]);
                    mma_bf16(acc[mt][nt], alf[mt], bhf[nt]);
                }
        }
    }

#pragma unroll
    for (int mt = 0; mt < 2; mt++) {
#pragma unroll
        for (int nt = 0; nt < 4; nt++) {
            int mrow = m0 + wm * 32 + mt * 16 + g;
            int ncol = n0 + wn * 32 + nt * 8 + tg * 2;
            float bx = bias[ncol], by = bias[ncol + 1];
#pragma unroll
            for (int half = 0; half < 2; half++) {
                int m = mrow + half * 8;
                float2 o;
                o.x = acc[mt][nt][half * 2 + 0] + bx;
                o.y = acc[mt][nt][half * 2 + 1] + by;
                float* dst;
                if (permC) {
                    int b = m & (B_ - 1);
                    int t = m >> 5;
                    dst = Cout + ((size_t)b * S_ + t) * ldc + ncol;
                } else {
                    dst = g_gx + (size_t)m * ldc + col0 + ncol;
                }
                *(float2*)dst = o;
            }
        }
    }
}

// ---------------------------------------------------------------------------
// Wavefront recurrence. Block bx owns cols [8bx, 8bx+8) for BOTH layers.
// Super-step k: layer1 step k (k<512), layer2 step k-1 (k>=1).
//   Phase A: stage h1,h2 tiles; compute z1,r1 (h1 x Wzh1/Wrh1),
//            z2,r2 (h1 x Wzx2/Wrx2 + h2 x Wzh2/Wrh2), gx2g (h1 x Wgx2).
//   Phase B: stage rh1,rh2 tiles; g1,g2; h updates (fp32 masters in regs).
// ---------------------------------------------------------------------------
#define SW_PW 516
#define TILE_B (32 * SW_PW * 4)             /* 66048 per tile */
#define WX_PITCH 516                        /* words per weight row (pad 4) */
#define WX_SET (8 * WX_PITCH)               /* 4128 words per set */
#define WX_B (3 * WX_SET * 4)               /* 49536 */
#define RED_STRIDE 42
#define RED_B (8 * 32 * RED_STRIDE * 4)     /* 43008 */
#define SMEMR (2 * TILE_B + WX_B + RED_B)   /* 224640 */

__device__ __forceinline__ void stage_warp(
    const unsigned short* __restrict__ gsrc, uint32_t* __restrict__ s,
    int warp, int lane)
{
    const int colq = warp * 16 + (lane & 15);
    const int rb = lane >> 4;
#pragma unroll
    for (int half = 0; half < 2; half++) {
        uint4 v[8];
#pragma unroll
        for (int it = 0; it < 8; it++) {
            int row = (half * 8 + it) * 2 + rb;
            v[it] = __ldcg((const uint4*)(gsrc + (size_t)row * H_) + colq);
        }
#pragma unroll
        for (int it = 0; it < 8; it++) {
            int row = (half * 8 + it) * 2 + rb;
            *(uint4*)(s + row * SW_PW + colq * 4) = v[it];
        }
    }
}

// load a-fragment (2 m-tiles) from a staged tile at k-word kw
#define LOAD_AFRAG(dst, tile, kw)                                  \
    do {                                                           \
        _Pragma("unroll")                                          \
        for (int mt = 0; mt < 2; mt++) {                           \
            const uint32_t* b0 = (tile) + (mt * 16 + g) * SW_PW;   \
            const uint32_t* b1 = b0 + 8 * SW_PW;                   \
            (dst)[mt][0] = b0[(kw)];                               \
            (dst)[mt][1] = b1[(kw)];                               \
            (dst)[mt][2] = b0[(kw) + 4];                           \
            (dst)[mt][3] = b1[(kw) + 4];                           \
        }                                                          \
    } while (0)

__global__ void __launch_bounds__(256, 1) k_gru_wave(
    const float* __restrict__ h0,
    const float* __restrict__ bz, const float* __restrict__ br,
    const float* __restrict__ bg, float* __restrict__ hid_out)
{
    extern __shared__ char smem[];
    uint32_t* s_t1 = (uint32_t*)smem;                          // h1/rh1 tile
    uint32_t* s_t2 = (uint32_t*)(smem + TILE_B);               // h2/rh2 tile
    uint32_t* s_wx = (uint32_t*)(smem + 2 * TILE_B);           // x2 weights
    float*    red  = (float*)(smem + 2 * TILE_B + WX_B);       // [8][32][42]

    const int tid = threadIdx.x;
    const int warp = tid >> 5, lane = tid & 31;
    const int g = lane >> 2, tg = lane & 3;

    const int c0 = blockIdx.x * 8;

    // ---- layer2 x-weights -> smem (pitch 516 words, conflict-free) ----
    {
        const uint32_t* wz = (const uint32_t*)(g_wzx2f + (size_t)c0 * H_);
        const uint32_t* wr = (const uint32_t*)(g_wrx2f + (size_t)c0 * H_);
        const uint32_t* wg = (const uint32_t*)(g_wgx2f + (size_t)c0 * H_);
        for (int idx = tid; idx < 8 * 512; idx += 256) {
            int row = idx >> 9, word = idx & 511;
            s_wx[0 * WX_SET + row * WX_PITCH + word] = wz[row * 512 + word];
            s_wx[1 * WX_SET + row * WX_PITCH + word] = wr[row * 512 + word];
            s_wx[2 * WX_SET + row * WX_PITCH + word] = wg[row * 512 + word];
        }
    }

    // ---- register weight fragments: 6 sets x 8 ks x 2 words ----
    uint32_t wz1[8][2], wr1[8][2], wg1[8][2];
    uint32_t wz2[8][2], wr2[8][2], wg2[8][2];
    {
        const size_t r1 = (size_t)(c0 + g) * H_;            // layer1 rows
        const size_t r2 = (size_t)H_ * H_ + r1;             // layer2 rows
#pragma unroll
        for (int ks = 0; ks < 8; ks++) {
            int kw = warp * 64 + ks * 8 + tg;
            wz1[ks][0] = ((const uint32_t*)(g_wzhf))[r1 / 2 + kw];
            wz1[ks][1] = ((const uint32_t*)(g_wzhf))[r1 / 2 + kw + 4];
            wr1[ks][0] = ((const uint32_t*)(g_wrhf))[r1 / 2 + kw];
            wr1[ks][1] = ((const uint32_t*)(g_wrhf))[r1 / 2 + kw + 4];
            wg1[ks][0] = ((const uint32_t*)(g_wghf))[r1 / 2 + kw];
            wg1[ks][1] = ((const uint32_t*)(g_wghf))[r1 / 2 + kw + 4];
            wz2[ks][0] = ((const uint32_t*)(g_wzhf))[r2 / 2 + kw];
            wz2[ks][1] = ((const uint32_t*)(g_wzhf))[r2 / 2 + kw + 4];
            wr2[ks][0] = ((const uint32_t*)(g_wrhf))[r2 / 2 + kw];
            wr2[ks][1] = ((const uint32_t*)(g_wrhf))[r2 / 2 + kw + 4];
            wg2[ks][0] = ((const uint32_t*)(g_wghf))[r2 / 2 + kw];
            wg2[ks][1] = ((const uint32_t*)(g_wghf))[r2 / 2 + kw + 4];
        }
    }

    // ---- per-thread state: (b=eb, col=j) ----
    const int eb = tid >> 3, ec = tid & 7;
    const int j = c0 + ec;

    float hv1 = h0[((size_t)eb * L_ + 0) * H_ + j];
    float hv2 = h0[((size_t)eb * L_ + 1) * H_ + j];
    const float bz2j = bz[H_ + j], br2j = br[H_ + j], bg2j = bg[H_ + j];

    float gxz1 = __ldcg(&g_gx[(size_t)eb * N3_ + j]);
    float gxr1 = __ldcg(&g_gx[(size_t)eb * N3_ + H_ + j]);

    float z1reg = 0.f, z2reg = 0.f, vgx2 = 0.f;

    for (int k = 0; k <= S_; k++) {
        const bool l1 = (k < S_);
        const bool l2 = (k >= 1);

        // phase-2 gx for layer1 (own col, constant buffer)
        float gxg1 = 0.f;
        if (l1) gxg1 = __ldcg(&g_gx[((size_t)k * B_ + eb) * N3_ + 2 * H_ + j]);

        // ================= phase A =================
        stage_warp(g_h1f, s_t1, warp, lane);
        stage_warp(g_h2f, s_t2, warp, lane);
        __syncwarp();

        float aZ1[2][4], aR1[2][4], aZ2[2][4], aR2[2][4], aG2[2][4];
#pragma unroll
        for (int mt = 0; mt < 2; mt++)
#pragma unroll
            for (int i = 0; i < 4; i++) {
                aZ1[mt][i] = 0.f; aR1[mt][i] = 0.f;
                aZ2[mt][i] = 0.f; aR2[mt][i] = 0.f; aG2[mt][i] = 0.f;
            }

#pragma unroll
        for (int ks = 0; ks < 8; ks++) {
            const int kw = warp * 64 + ks * 8 + tg;
            uint32_t a1[2][4], a2[2][4];
            LOAD_AFRAG(a1, s_t1, kw);
            LOAD_AFRAG(a2, s_t2, kw);
            uint32_t wzx[2], wrx[2], wgx[2];
            {
                int wo = g * WX_PITCH + kw;
                wzx[0] = s_wx[wo];             wzx[1] = s_wx[wo + 4];
                wrx[0] = s_wx[WX_SET + wo];    wrx[1] = s_wx[WX_SET + wo + 4];
                wgx[0] = s_wx[2 * WX_SET + wo]; wgx[1] = s_wx[2 * WX_SET + wo + 4];
            }
#pragma unroll
            for (int mt = 0; mt < 2; mt++) {
                mma_f16(aZ1[mt], a1[mt], wz1[ks]);
                mma_f16(aR1[mt], a1[mt], wr1[ks]);
                mma_f16(aZ2[mt], a1[mt], wzx);
                mma_f16(aZ2[mt], a2[mt], wz2[ks]);
                mma_f16(aR2[mt], a1[mt], wrx);
                mma_f16(aR2[mt], a2[mt], wr2[ks]);
                mma_f16(aG2[mt], a1[mt], wgx);
            }
        }

        // red: groups z1(0) r1(8) z2(16) r2(24) gx2(32)
#pragma unroll
        for (int mt = 0; mt < 2; mt++)
#pragma unroll
            for (int i = 0; i < 4; i++) {
                int brow = mt * 16 + g + (i >> 1) * 8;
                int cc = tg * 2 + (i & 1);
                float* rp = &red[(warp * 32 + brow) * RED_STRIDE + cc];
                rp[0]  = aZ1[mt][i];
                rp[8]  = aR1[mt][i];
                rp[16] = aZ2[mt][i];
                rp[24] = aR2[mt][i];
                rp[32] = aG2[mt][i];
            }
        __syncthreads();

        {
            if (l1) {
                float vz = 0.f, vr = 0.f;
#pragma unroll
                for (int w = 0; w < 8; w++) {
                    const float* rp = &red[(w * 32 + eb) * RED_STRIDE + ec];
                    vz += rp[0];
                    vr += rp[8];
                }
                z1reg = sigmoidf_(vz + gxz1);
                float r1 = sigmoidf_(vr + gxr1);
                g_rh1f[eb * H_ + j] = __half_as_ushort(__float2half(r1 * hv1));
            }
            if (l2) {
                float vz = 0.f, vr = 0.f, vg = 0.f;
#pragma unroll
                for (int w = 0; w < 8; w++) {
                    const float* rp = &red[(w * 32 + eb) * RED_STRIDE + ec];
                    vz += rp[16];
                    vr += rp[24];
                    vg += rp[32];
                }
                z2reg = sigmoidf_(vz + bz2j);
                float r2 = sigmoidf_(vr + br2j);
                g_rh2f[eb * H_ + j] = __half_as_ushort(__float2half(r2 * hv2));
                vgx2 = vg;
            }
        }

        grid_sync();

        // ================= phase B =================
        stage_warp(g_rh1f, s_t1, warp, lane);
        stage_warp(g_rh2f, s_t2, warp, lane);
        __syncwarp();

        float aG1[2][4], bG2[2][4];
#pragma unroll
        for (int mt = 0; mt < 2; mt++)
#pragma unroll
            for (int i = 0; i < 4; i++) { aG1[mt][i] = 0.f; bG2[mt][i] = 0.f; }

#pragma unroll
        for (int ks = 0; ks < 8; ks++) {
            const int kw = warp * 64 + ks * 8 + tg;
            uint32_t a1[2][4], a2[2][4];
            LOAD_AFRAG(a1, s_t1, kw);
            LOAD_AFRAG(a2, s_t2, kw);
#pragma unroll
            for (int mt = 0; mt < 2; mt++) {
                mma_f16(aG1[mt], a1[mt], wg1[ks]);
                mma_f16(bG2[mt], a2[mt], wg2[ks]);
            }
        }

#pragma unroll
        for (int mt = 0; mt < 2; mt++)
#pragma unroll
            for (int i = 0; i < 4; i++) {
                int brow = mt * 16 + g + (i >> 1) * 8;
                int cc = tg * 2 + (i & 1);
                float* rp = &red[(warp * 32 + brow) * RED_STRIDE + cc];
                rp[0] = aG1[mt][i];
                rp[8] = bG2[mt][i];
            }
        __syncthreads();

        {
            if (l1) {
                float v = 0.f;
#pragma unroll
                for (int w = 0; w < 8; w++)
                    v += red[(w * 32 + eb) * RED_STRIDE + ec];
                float gv = tanhf(v + gxg1);
                hv1 = fmaf(z1reg, gv - hv1, hv1);
                g_h1f[eb * H_ + j] = __half_as_ushort(__float2half(hv1));
                if (k == S_ - 1)
                    hid_out[((size_t)eb * L_ + 0) * H_ + j] = hv1;
            }
            if (l2) {
                float v = 0.f;
#pragma unroll
                for (int w = 0; w < 8; w++)
                    v += red[(w * 32 + eb) * RED_STRIDE + 8 + ec];
                float gv = tanhf(v + vgx2 + bg2j);
                hv2 = fmaf(z2reg, gv - hv2, hv2);
                g_h2f[eb * H_ + j] = __half_as_ushort(__float2half(hv2));
                unsigned short bh, bl;
                split1(hv2, bh, bl);
                size_t srow = (size_t)(k - 1) * B_ + eb;
                g_seqh[srow * H_ + j] = bh;
                g_seql[srow * H_ + j] = bl;
                if (k == S_)
                    hid_out[((size_t)eb * L_ + 1) * H_ + j] = hv2;
            }
        }

        // prefetch next phase-1 gx (constant data)
        if (k + 1 < S_) {
            gxz1 = __ldcg(&g_gx[((size_t)(k + 1) * B_ + eb) * N3_ + j]);
            gxr1 = __ldcg(&g_gx[((size_t)(k + 1) * B_ + eb) * N3_ + H_ + j]);
        }

        grid_sync();
    }
}

// ---------------------------------------------------------------------------
// Launch
// ---------------------------------------------------------------------------
extern "C" void kernel_launch(void* const* d_in, const int* in_sizes, int n_in,
                              void* d_out, int out_size) {
    (void)in_sizes; (void)n_in;
    const float* x   = (const float*)d_in[0];
    const float* h0  = (const float*)d_in[1];
    const float* Wzx = (const float*)d_in[2];
    const float* bz  = (const float*)d_in[3];
    const float* Wzh = (const float*)d_in[4];
    const float* Wrx = (const float*)d_in[5];
    const float* br  = (const float*)d_in[6];
    const float* Wrh = (const float*)d_in[7];
    const float* Wgx = (const float*)d_in[8];
    const float* bg  = (const float*)d_in[9];
    const float* Wgh = (const float*)d_in[10];
    const float* Wo  = (const float*)d_in[11];
    const float* bo  = (const float*)d_in[12];

    float* out = (float*)d_out;
    float* y_out = out;
    const long long need = (long long)B_ * S_ * OUT_ + (long long)B_ * L_ * H_;
    float* hid_out = ((long long)out_size >= need) ? out + (size_t)B_ * S_ * OUT_
                                                   : nullptr;

    cudaFuncSetAttribute(k_gru_wave,
        cudaFuncAttributeMaxDynamicSharedMemorySize, SMEMR);

    // operand prep
    k_transpose_x<<<M_, 256>>>(x);
    const int w1g4 = (H_ * IN_) / 4;         // 262144 (one layer slice)
    const int w2g4 = (L_ * H_ * H_) / 4;     // 524288 (both layers)
    k_split<<<w1g4 / 256, 256>>>(Wzx, 0, w1g4);              // layer-1 slice
    k_split<<<w1g4 / 256, 256>>>(Wrx, 1, w1g4);
    k_split<<<w1g4 / 256, 256>>>(Wgx, 2, w1g4);
    k_split<<<w1g4 / 256, 256>>>(Wo,  3, w1g4);
    k_split16<<<w2g4 / 256, 256>>>(Wzh, 0, w2g4);
    k_split16<<<w2g4 / 256, 256>>>(Wrh, 1, w2g4);
    k_split16<<<w2g4 / 256, 256>>>(Wgh, 2, w2g4);
    k_split16<<<w1g4 / 256, 256>>>(Wzx + (size_t)H_ * IN_, 3, w1g4);  // layer-2 x-weights
    k_split16<<<w1g4 / 256, 256>>>(Wrx + (size_t)H_ * IN_, 4, w1g4);
    k_split16<<<w1g4 / 256, 256>>>(Wgx + (size_t)H_ * IN_, 5, w1g4);

    k_prep<<<(B_ * H_) / 256, 256>>>(h0);

    // layer-1 x-projections (big GEMMs)
    dim3 tgrid(1024 / 64, M_ / 128);   // (16, 128)
    k_hmma<<<tgrid, 256>>>(0, 0, bz, nullptr, N3_, 0, 0);
    k_hmma<<<tgrid, 256>>>(0, 1, br, nullptr, N3_, H_, 0);
    k_hmma<<<tgrid, 256>>>(0, 2, bg, nullptr, N3_, 2 * H_, 0);

    // wavefront recurrence: both layers, 513 super-steps, ONE launch
    k_gru_wave<<<NBLK, 256, SMEMR>>>(h0, bz, br, bg, hid_out);

    // output projection
    k_hmma<<<tgrid, 256>>>(1, 3, bo, y_out, OUT_, 0, 1);
}

// round 16
// speedup vs baseline: 1.8536x; 1.1886x over previous
#include <cuda_runtime.h>
#include <cuda_fp16.h>
#include <math.h>
#include <stdint.h>

// ---------------------------------------------------------------------------
// MultilayerGRU: B=32, S=512, I=H=O=1024, L=2
// R16 = R15 bugfix: k_hmma16 selects its weight buffer DEVICE-SIDE via wsel
// (R15 passed a __device__ symbol from host -> host shadow address -> illegal
// access -> dead context -> rel_err 1.0).
//  - x-projections: single-fp16 HMMA GEMM.
//  - output projection fused into wavefront phase A (Wo fp16 hi/lo, 2 terms).
//  - wavefront recurrence structure = R14 (proven 7.38ms).
// ---------------------------------------------------------------------------

#define B_  32
#define S_  512
#define IN_ 1024
#define H_  1024
#define OUT_ 1024
#define L_  2
#define M_  (B_ * S_)      /* 16384 */
#define N3_ (3 * H_)       /* 3072  */
#define NBLK 128

// ---------------- device scratch ------------------------------------------
__device__ float g_gx[(size_t)M_ * N3_];   // layer-1 x-projections

__device__ __align__(16) unsigned short g_h1f[B_ * H_];   // h1 fp16
__device__ __align__(16) unsigned short g_h2f[B_ * H_];   // h2 fp16
__device__ __align__(16) unsigned short g_rh1f[B_ * H_];  // r1*h1 fp16
__device__ __align__(16) unsigned short g_rh2f[B_ * H_];  // r2*h2 fp16

__device__ __align__(16) unsigned short g_xf[(size_t)M_ * IN_];   // x fp16

// fp16 weights
__device__ __align__(16) unsigned short g_wzx1f[(size_t)H_ * IN_];
__device__ __align__(16) unsigned short g_wrx1f[(size_t)H_ * IN_];
__device__ __align__(16) unsigned short g_wgx1f[(size_t)H_ * IN_];
__device__ __align__(16) unsigned short g_wzhf[(size_t)L_ * H_ * H_];
__device__ __align__(16) unsigned short g_wrhf[(size_t)L_ * H_ * H_];
__device__ __align__(16) unsigned short g_wghf[(size_t)L_ * H_ * H_];
__device__ __align__(16) unsigned short g_wzx2f[(size_t)H_ * H_];
__device__ __align__(16) unsigned short g_wrx2f[(size_t)H_ * H_];
__device__ __align__(16) unsigned short g_wgx2f[(size_t)H_ * H_];
__device__ __align__(16) unsigned short g_wohf[(size_t)OUT_ * H_];  // Wo hi
__device__ __align__(16) unsigned short g_wolf[(size_t)OUT_ * H_];  // Wo lo

// flat grid barrier (reset by k_prep)
__device__ unsigned g_bar_count;
__device__ volatile unsigned g_bar_gen;

__device__ __forceinline__ void grid_sync() {
    __syncthreads();
    if (threadIdx.x == 0) {
        __threadfence();
        unsigned gen = g_bar_gen;
        if (atomicAdd(&g_bar_count, 1u) == NBLK - 1u) {
            g_bar_count = 0;
            __threadfence();
            g_bar_gen = gen + 1u;
        } else {
            while (g_bar_gen == gen) { }
        }
    }
    __syncthreads();
}

// ---------------------------------------------------------------------------
__device__ __forceinline__ void split16(float v, unsigned short& h, unsigned short& l) {
    __half hh = __float2half(v);
    float r = v - __half2float(hh);
    h = __half_as_ushort(hh);
    l = __half_as_ushort(__float2half(r));
}

__device__ __forceinline__ void mma_f16(float* c, const uint32_t* a, const uint32_t* b) {
    asm volatile(
        "mma.sync.aligned.m16n8k16.row.col.f32.f16.f16.f32 "
        "{%0,%1,%2,%3}, {%4,%5,%6,%7}, {%8,%9}, {%0,%1,%2,%3};"
        : "+f"(c[0]), "+f"(c[1]), "+f"(c[2]), "+f"(c[3])
        : "r"(a[0]), "r"(a[1]), "r"(a[2]), "r"(a[3]), "r"(b[0]), "r"(b[1]));
}

__device__ __forceinline__ float sigmoidf_(float x) {
    return 1.f / (1.f + expf(-x));
}

// ---------------------------------------------------------------------------
// x[b][t][i] -> fp16 [t*B+b][i]
// ---------------------------------------------------------------------------
__global__ void k_transpose_x(const float* __restrict__ x) {
    int row = blockIdx.x;
    int t = row / B_;
    int b = row % B_;
    const float4* src = (const float4*)(x + ((size_t)b * S_ + t) * IN_);
    ushort4* dh = (ushort4*)(g_xf + (size_t)row * IN_);
    for (int i = threadIdx.x; i < IN_ / 4; i += blockDim.x) {
        float4 v = src[i];
        ushort4 h;
        h.x = __half_as_ushort(__float2half(v.x));
        h.y = __half_as_ushort(__float2half(v.y));
        h.z = __half_as_ushort(__float2half(v.z));
        h.w = __half_as_ushort(__float2half(v.w));
        dh[i] = h;
    }
}

// ---------------------------------------------------------------------------
// weight splits (fp16 single; wsel 9 = Wo hi/lo)
// ---------------------------------------------------------------------------
__global__ void k_split16(const float* __restrict__ src, int wsel, int n4) {
    int i = blockIdx.x * blockDim.x + threadIdx.x;
    if (i >= n4) return;
    float4 v = ((const float4*)src)[i];
    if (wsel == 9) {
        ushort4 h, l;
        split16(v.x, h.x, l.x);
        split16(v.y, h.y, l.y);
        split16(v.z, h.z, l.z);
        split16(v.w, h.w, l.w);
        ((ushort4*)g_wohf)[i] = h;
        ((ushort4*)g_wolf)[i] = l;
        return;
    }
    unsigned short* hi;
    switch (wsel) {
        case 0: hi = g_wzhf;  break;
        case 1: hi = g_wrhf;  break;
        case 2: hi = g_wghf;  break;
        case 3: hi = g_wzx2f; break;
        case 4: hi = g_wrx2f; break;
        case 5: hi = g_wgx2f; break;
        case 6: hi = g_wzx1f; break;
        case 7: hi = g_wrx1f; break;
        default: hi = g_wgx1f; break;
    }
    ushort4 h;
    h.x = __half_as_ushort(__float2half(v.x));
    h.y = __half_as_ushort(__float2half(v.y));
    h.z = __half_as_ushort(__float2half(v.z));
    h.w = __half_as_ushort(__float2half(v.w));
    ((ushort4*)hi)[i] = h;
}

// ---------------------------------------------------------------------------
// k_prep: fp16 h states from h0; reset barrier.
// ---------------------------------------------------------------------------
__global__ void k_prep(const float* __restrict__ h0) {
    int idx = blockIdx.x * blockDim.x + threadIdx.x;  // [0, B*H)
    if (idx == 0) { g_bar_count = 0; g_bar_gen = 0; }
    int b = idx / H_;
    int c = idx % H_;
    g_h1f[idx] = __half_as_ushort(__float2half(h0[((size_t)b * L_ + 0) * H_ + c]));
    g_h2f[idx] = __half_as_ushort(__float2half(h0[((size_t)b * L_ + 1) * H_ + c]));
}

// ---------------------------------------------------------------------------
// Single-fp16 HMMA GEMM: g_gx[m][col0+n] = sum_k x[m][k]*W[n][k] + bias[n]
//   W selected DEVICE-SIDE via wsel (0=Wzx1, 1=Wrx1, 2=Wgx1).
// ---------------------------------------------------------------------------
#define HMP 40

__global__ void __launch_bounds__(256) k_hmma16(
    int wsel, const float* __restrict__ bias, int col0)
{
    __shared__ __align__(16) unsigned short As[128 * HMP];
    __shared__ __align__(16) unsigned short Bs[64 * HMP];

    const int tid = threadIdx.x;
    const int m0 = blockIdx.y * 128, n0 = blockIdx.x * 64;

    const unsigned short* A = g_xf;
    const unsigned short* W = (wsel == 0) ? g_wzx1f
                            : (wsel == 1) ? g_wrx1f : g_wgx1f;

    const int ar0 = (2 * tid) >> 2,     au0 = (2 * tid) & 3;
    const int ar1 = (2 * tid + 1) >> 2, au1 = (2 * tid + 1) & 3;
    const int br  = tid >> 2,           bu  = tid & 3;

    const int warp = tid >> 5, lane = tid & 31;
    const int g = lane >> 2, tg = lane & 3;
    const int wm = warp >> 1, wn = warp & 1;

    float acc[2][4][4];
#pragma unroll
    for (int mt = 0; mt < 2; mt++)
#pragma unroll
        for (int nt = 0; nt < 4; nt++)
#pragma unroll
            for (int i = 0; i < 4; i++) acc[mt][nt][i] = 0.f;

    const uint32_t* Aw = (const uint32_t*)As;
    const uint32_t* Bw = (const uint32_t*)Bs;

    uint4 va0, va1, vb;
    va0 = *(const uint4*)(A + (size_t)(m0 + ar0) * 1024 + au0 * 8);
    va1 = *(const uint4*)(A + (size_t)(m0 + ar1) * 1024 + au1 * 8);
    vb  = *(const uint4*)(W + (size_t)(n0 + br) * 1024 + bu * 8);

    for (int kc = 0; kc < 32; kc++) {
        __syncthreads();
        *(uint4*)(As + ar0 * HMP + au0 * 8) = va0;
        *(uint4*)(As + ar1 * HMP + au1 * 8) = va1;
        *(uint4*)(Bs + br * HMP + bu * 8) = vb;
        if (kc + 1 < 32) {
            int ko = (kc + 1) * 32;
            va0 = *(const uint4*)(A + (size_t)(m0 + ar0) * 1024 + ko + au0 * 8);
            va1 = *(const uint4*)(A + (size_t)(m0 + ar1) * 1024 + ko + au1 * 8);
            vb  = *(const uint4*)(W + (size_t)(n0 + br) * 1024 + ko + bu * 8);
        }
        __syncthreads();

#pragma unroll
        for (int ks = 0; ks < 2; ks++) {
            const int kw = ks * 8 + tg;
            uint32_t af[2][4];
#pragma unroll
            for (int mt = 0; mt < 2; mt++) {
                int rb = (wm * 32 + mt * 16 + g) * 20 + kw;
                af[mt][0] = Aw[rb];
                af[mt][1] = Aw[rb + 160];
                af[mt][2] = Aw[rb + 4];
                af[mt][3] = Aw[rb + 164];
            }
            uint32_t bf[4][2];
#pragma unroll
            for (int nt = 0; nt < 4; nt++) {
                int rb = (wn * 32 + nt * 8 + g) * 20 + kw;
                bf[nt][0] = Bw[rb];
                bf[nt][1] = Bw[rb + 4];
            }
#pragma unroll
            for (int mt = 0; mt < 2; mt++)
#pragma unroll
                for (int nt = 0; nt < 4; nt++)
                    mma_f16(acc[mt][nt], af[mt], bf[nt]);
        }
    }

#pragma unroll
    for (int mt = 0; mt < 2; mt++) {
#pragma unroll
        for (int nt = 0; nt < 4; nt++) {
            int mrow = m0 + wm * 32 + mt * 16 + g;
            int ncol = n0 + wn * 32 + nt * 8 + tg * 2;
            float bx = bias[ncol], by = bias[ncol + 1];
#pragma unroll
            for (int half = 0; half < 2; half++) {
                int m = mrow + half * 8;
                float2 o;
                o.x = acc[mt][nt][half * 2 + 0] + bx;
                o.y = acc[mt][nt][half * 2 + 1] + by;
                *(float2*)(g_gx + (size_t)m * N3_ + col0 + ncol) = o;
            }
        }
    }
}

// ---------------------------------------------------------------------------
// Wavefront recurrence + fused output projection.
// Super-step k (0..S+1): layer1 step k (k<S), layer2 step k-1 (1<=k<=S),
// y(k-2) from the phase-A-staged h2 tile (2<=k<=S+1).
// ---------------------------------------------------------------------------
#define SW_PW 516
#define TILE_B (32 * SW_PW * 4)             /* 66048 per tile */
#define WX_PITCH 516
#define WX_SET (8 * WX_PITCH)
#define WX_B (3 * WX_SET * 4)               /* 49536 */
#define RED_STRIDE 42
#define RED_B (8 * 32 * RED_STRIDE * 4)     /* 43008 */
#define SMEMR (2 * TILE_B + WX_B + RED_B)   /* 224640 */

__device__ __forceinline__ void stage_warp(
    const unsigned short* __restrict__ gsrc, uint32_t* __restrict__ s,
    int warp, int lane)
{
    const int colq = warp * 16 + (lane & 15);
    const int rb = lane >> 4;
#pragma unroll
    for (int half = 0; half < 2; half++) {
        uint4 v[8];
#pragma unroll
        for (int it = 0; it < 8; it++) {
            int row = (half * 8 + it) * 2 + rb;
            v[it] = __ldcg((const uint4*)(gsrc + (size_t)row * H_) + colq);
        }
#pragma unroll
        for (int it = 0; it < 8; it++) {
            int row = (half * 8 + it) * 2 + rb;
            *(uint4*)(s + row * SW_PW + colq * 4) = v[it];
        }
    }
}

#define LOAD_AFRAG(dst, tile, kw)                                  \
    do {                                                           \
        _Pragma("unroll")                                          \
        for (int mt = 0; mt < 2; mt++) {                           \
            const uint32_t* b0 = (tile) + (mt * 16 + g) * SW_PW;   \
            const uint32_t* b1 = b0 + 8 * SW_PW;                   \
            (dst)[mt][0] = b0[(kw)];                               \
            (dst)[mt][1] = b1[(kw)];                               \
            (dst)[mt][2] = b0[(kw) + 4];                           \
            (dst)[mt][3] = b1[(kw) + 4];                           \
        }                                                          \
    } while (0)

__global__ void __launch_bounds__(256, 1) k_gru_wave(
    const float* __restrict__ h0,
    const float* __restrict__ bz, const float* __restrict__ br,
    const float* __restrict__ bg, const float* __restrict__ bo,
    float* __restrict__ y_out, float* __restrict__ hid_out)
{
    extern __shared__ char smem[];
    uint32_t* s_t1 = (uint32_t*)smem;                          // h1/rh1 tile
    uint32_t* s_t2 = (uint32_t*)(smem + TILE_B);               // h2/rh2 tile
    uint32_t* s_wx = (uint32_t*)(smem + 2 * TILE_B);           // x2 weights
    float*    red  = (float*)(smem + 2 * TILE_B + WX_B);       // [8][32][42]

    const int tid = threadIdx.x;
    const int warp = tid >> 5, lane = tid & 31;
    const int g = lane >> 2, tg = lane & 3;

    const int c0 = blockIdx.x * 8;

    // ---- layer2 x-weights -> smem ----
    {
        const uint32_t* wz = (const uint32_t*)(g_wzx2f + (size_t)c0 * H_);
        const uint32_t* wr = (const uint32_t*)(g_wrx2f + (size_t)c0 * H_);
        const uint32_t* wg = (const uint32_t*)(g_wgx2f + (size_t)c0 * H_);
        for (int idx = tid; idx < 8 * 512; idx += 256) {
            int row = idx >> 9, word = idx & 511;
            s_wx[0 * WX_SET + row * WX_PITCH + word] = wz[row * 512 + word];
            s_wx[1 * WX_SET + row * WX_PITCH + word] = wr[row * 512 + word];
            s_wx[2 * WX_SET + row * WX_PITCH + word] = wg[row * 512 + word];
        }
    }
    __syncthreads();   // s_wx visible to all warps before first use

    // ---- register weight fragments ----
    uint32_t wz1[8][2], wr1[8][2], wg1[8][2];
    uint32_t wz2[8][2], wr2[8][2], wg2[8][2];
    uint32_t woh[8][2], wol[8][2];
    {
        const size_t r1 = (size_t)(c0 + g) * H_;            // layer1 rows
        const size_t r2 = (size_t)H_ * H_ + r1;             // layer2 rows
#pragma unroll
        for (int ks = 0; ks < 8; ks++) {
            int kw = warp * 64 + ks * 8 + tg;
            wz1[ks][0] = ((const uint32_t*)(g_wzhf))[r1 / 2 + kw];
            wz1[ks][1] = ((const uint32_t*)(g_wzhf))[r1 / 2 + kw + 4];
            wr1[ks][0] = ((const uint32_t*)(g_wrhf))[r1 / 2 + kw];
            wr1[ks][1] = ((const uint32_t*)(g_wrhf))[r1 / 2 + kw + 4];
            wg1[ks][0] = ((const uint32_t*)(g_wghf))[r1 / 2 + kw];
            wg1[ks][1] = ((const uint32_t*)(g_wghf))[r1 / 2 + kw + 4];
            wz2[ks][0] = ((const uint32_t*)(g_wzhf))[r2 / 2 + kw];
            wz2[ks][1] = ((const uint32_t*)(g_wzhf))[r2 / 2 + kw + 4];
            wr2[ks][0] = ((const uint32_t*)(g_wrhf))[r2 / 2 + kw];
            wr2[ks][1] = ((const uint32_t*)(g_wrhf))[r2 / 2 + kw + 4];
            wg2[ks][0] = ((const uint32_t*)(g_wghf))[r2 / 2 + kw];
            wg2[ks][1] = ((const uint32_t*)(g_wghf))[r2 / 2 + kw + 4];
            woh[ks][0] = ((const uint32_t*)(g_wohf))[r1 / 2 + kw];
            woh[ks][1] = ((const uint32_t*)(g_wohf))[r1 / 2 + kw + 4];
            wol[ks][0] = ((const uint32_t*)(g_wolf))[r1 / 2 + kw];
            wol[ks][1] = ((const uint32_t*)(g_wolf))[r1 / 2 + kw + 4];
        }
    }

    // ---- per-thread state: (b=eb, col=j) ----
    const int eb = tid >> 3, ec = tid & 7;
    const int j = c0 + ec;

    float hv1 = h0[((size_t)eb * L_ + 0) * H_ + j];
    float hv2 = h0[((size_t)eb * L_ + 1) * H_ + j];
    const float bz2j = bz[H_ + j], br2j = br[H_ + j], bg2j = bg[H_ + j];
    const float boj = bo[j];

    float gxz1 = __ldcg(&g_gx[(size_t)eb * N3_ + j]);
    float gxr1 = __ldcg(&g_gx[(size_t)eb * N3_ + H_ + j]);

    float z1reg = 0.f, z2reg = 0.f, vgx2 = 0.f;
    float yacc[2][4];

    for (int k = 0; k <= S_ + 1; k++) {
        const bool l1 = (k < S_);
        const bool l2 = (k >= 1 && k <= S_);
        const bool ly = (k >= 2);

        float gxg1 = 0.f;
        if (l1) gxg1 = __ldcg(&g_gx[((size_t)k * B_ + eb) * N3_ + 2 * H_ + j]);

        // ================= phase A =================
        stage_warp(g_h1f, s_t1, warp, lane);
        stage_warp(g_h2f, s_t2, warp, lane);
        __syncwarp();

        float aZ1[2][4], aR1[2][4], aZ2[2][4], aR2[2][4], aG2[2][4];
#pragma unroll
        for (int mt = 0; mt < 2; mt++)
#pragma unroll
            for (int i = 0; i < 4; i++) {
                aZ1[mt][i] = 0.f; aR1[mt][i] = 0.f;
                aZ2[mt][i] = 0.f; aR2[mt][i] = 0.f; aG2[mt][i] = 0.f;
                yacc[mt][i] = 0.f;
            }

#pragma unroll
        for (int ks = 0; ks < 8; ks++) {
            const int kw = warp * 64 + ks * 8 + tg;
            uint32_t a1[2][4], a2[2][4];
            LOAD_AFRAG(a1, s_t1, kw);
            LOAD_AFRAG(a2, s_t2, kw);
            uint32_t wzx[2], wrx[2], wgx[2];
            {
                int wo = g * WX_PITCH + kw;
                wzx[0] = s_wx[wo];              wzx[1] = s_wx[wo + 4];
                wrx[0] = s_wx[WX_SET + wo];     wrx[1] = s_wx[WX_SET + wo + 4];
                wgx[0] = s_wx[2 * WX_SET + wo]; wgx[1] = s_wx[2 * WX_SET + wo + 4];
            }
#pragma unroll
            for (int mt = 0; mt < 2; mt++) {
                mma_f16(aZ1[mt], a1[mt], wz1[ks]);
                mma_f16(aR1[mt], a1[mt], wr1[ks]);
                mma_f16(aZ2[mt], a1[mt], wzx);
                mma_f16(aZ2[mt], a2[mt], wz2[ks]);
                mma_f16(aR2[mt], a1[mt], wrx);
                mma_f16(aR2[mt], a2[mt], wr2[ks]);
                mma_f16(aG2[mt], a1[mt], wgx);
                mma_f16(yacc[mt], a2[mt], woh[ks]);
                mma_f16(yacc[mt], a2[mt], wol[ks]);
            }
        }

        // red: groups z1(0) r1(8) z2(16) r2(24) gx2(32)
#pragma unroll
        for (int mt = 0; mt < 2; mt++)
#pragma unroll
            for (int i = 0; i < 4; i++) {
                int brow = mt * 16 + g + (i >> 1) * 8;
                int cc = tg * 2 + (i & 1);
                float* rp = &red[(warp * 32 + brow) * RED_STRIDE + cc];
                rp[0]  = aZ1[mt][i];
                rp[8]  = aR1[mt][i];
                rp[16] = aZ2[mt][i];
                rp[24] = aR2[mt][i];
                rp[32] = aG2[mt][i];
            }
        __syncthreads();

        {
            if (l1) {
                float vz = 0.f, vr = 0.f;
#pragma unroll
                for (int w = 0; w < 8; w++) {
                    const float* rp = &red[(w * 32 + eb) * RED_STRIDE + ec];
                    vz += rp[0];
                    vr += rp[8];
                }
                z1reg = sigmoidf_(vz + gxz1);
                float r1 = sigmoidf_(vr + gxr1);
                g_rh1f[eb * H_ + j] = __half_as_ushort(__float2half(r1 * hv1));
            }
            if (l2) {
                float vz = 0.f, vr = 0.f, vg = 0.f;
#pragma unroll
                for (int w = 0; w < 8; w++) {
                    const float* rp = &red[(w * 32 + eb) * RED_STRIDE + ec];
                    vz += rp[16];
                    vr += rp[24];
                    vg += rp[32];
                }
                z2reg = sigmoidf_(vz + bz2j);
                float r2 = sigmoidf_(vr + br2j);
                g_rh2f[eb * H_ + j] = __half_as_ushort(__float2half(r2 * hv2));
                vgx2 = vg;
            }
        }

        grid_sync();

        // ================= phase B =================
        stage_warp(g_rh1f, s_t1, warp, lane);
        stage_warp(g_rh2f, s_t2, warp, lane);
        __syncwarp();

        float aG1[2][4], bG2[2][4];
#pragma unroll
        for (int mt = 0; mt < 2; mt++)
#pragma unroll
            for (int i = 0; i < 4; i++) { aG1[mt][i] = 0.f; bG2[mt][i] = 0.f; }

#pragma unroll
        for (int ks = 0; ks < 8; ks++) {
            const int kw = warp * 64 + ks * 8 + tg;
            uint32_t a1[2][4], a2[2][4];
            LOAD_AFRAG(a1, s_t1, kw);
            LOAD_AFRAG(a2, s_t2, kw);
#pragma unroll
            for (int mt = 0; mt < 2; mt++) {
                mma_f16(aG1[mt], a1[mt], wg1[ks]);
                mma_f16(bG2[mt], a2[mt], wg2[ks]);
            }
        }

        // red: g1(0) g2(8) y(16)
#pragma unroll
        for (int mt = 0; mt < 2; mt++)
#pragma unroll
            for (int i = 0; i < 4; i++) {
                int brow = mt * 16 + g + (i >> 1) * 8;
                int cc = tg * 2 + (i & 1);
                float* rp = &red[(warp * 32 + brow) * RED_STRIDE + cc];
                rp[0]  = aG1[mt][i];
                rp[8]  = bG2[mt][i];
                rp[16] = yacc[mt][i];
            }
        __syncthreads();

        {
            if (l1) {
                float v = 0.f;
#pragma unroll
                for (int w = 0; w < 8; w++)
                    v += red[(w * 32 + eb) * RED_STRIDE + ec];
                float gv = tanhf(v + gxg1);
                hv1 = fmaf(z1reg, gv - hv1, hv1);
                g_h1f[eb * H_ + j] = __half_as_ushort(__float2half(hv1));
                if (hid_out && k == S_ - 1)
                    hid_out[((size_t)eb * L_ + 0) * H_ + j] = hv1;
            }
            if (l2) {
                float v = 0.f;
#pragma unroll
                for (int w = 0; w < 8; w++)
                    v += red[(w * 32 + eb) * RED_STRIDE + 8 + ec];
                float gv = tanhf(v + vgx2 + bg2j);
                hv2 = fmaf(z2reg, gv - hv2, hv2);
                g_h2f[eb * H_ + j] = __half_as_ushort(__float2half(hv2));
                if (hid_out && k == S_)
                    hid_out[((size_t)eb * L_ + 1) * H_ + j] = hv2;
            }
            if (ly) {
                float v = 0.f;
#pragma unroll
                for (int w = 0; w < 8; w++)
                    v += red[(w * 32 + eb) * RED_STRIDE + 16 + ec];
                y_out[((size_t)eb * S_ + (k - 2)) * OUT_ + j] = v + boj;
            }
        }

        // prefetch next phase-A gx (constant data)
        if (k + 1 < S_) {
            gxz1 = __ldcg(&g_gx[((size_t)(k + 1) * B_ + eb) * N3_ + j]);
            gxr1 = __ldcg(&g_gx[((size_t)(k + 1) * B_ + eb) * N3_ + H_ + j]);
        }

        grid_sync();
    }
}

// ---------------------------------------------------------------------------
// Launch
// ---------------------------------------------------------------------------
extern "C" void kernel_launch(void* const* d_in, const int* in_sizes, int n_in,
                              void* d_out, int out_size) {
    (void)in_sizes; (void)n_in;
    const float* x   = (const float*)d_in[0];
    const float* h0  = (const float*)d_in[1];
    const float* Wzx = (const float*)d_in[2];
    const float* bz  = (const float*)d_in[3];
    const float* Wzh = (const float*)d_in[4];
    const float* Wrx = (const float*)d_in[5];
    const float* br  = (const float*)d_in[6];
    const float* Wrh = (const float*)d_in[7];
    const float* Wgx = (const float*)d_in[8];
    const float* bg  = (const float*)d_in[9];
    const float* Wgh = (const float*)d_in[10];
    const float* Wo  = (const float*)d_in[11];
    const float* bo  = (const float*)d_in[12];

    float* out = (float*)d_out;
    float* y_out = out;
    const long long need = (long long)B_ * S_ * OUT_ + (long long)B_ * L_ * H_;
    float* hid_out = ((long long)out_size >= need) ? out + (size_t)B_ * S_ * OUT_
                                                   : nullptr;

    cudaFuncSetAttribute(k_gru_wave,
        cudaFuncAttributeMaxDynamicSharedMemorySize, SMEMR);

    // operand prep (all fp16)
    k_transpose_x<<<M_, 256>>>(x);
    const int w1g4 = (H_ * IN_) / 4;         // 262144
    const int w2g4 = (L_ * H_ * H_) / 4;     // 524288
    k_split16<<<w2g4 / 256, 256>>>(Wzh, 0, w2g4);
    k_split16<<<w2g4 / 256, 256>>>(Wrh, 1, w2g4);
    k_split16<<<w2g4 / 256, 256>>>(Wgh, 2, w2g4);
    k_split16<<<w1g4 / 256, 256>>>(Wzx + (size_t)H_ * IN_, 3, w1g4);
    k_split16<<<w1g4 / 256, 256>>>(Wrx + (size_t)H_ * IN_, 4, w1g4);
    k_split16<<<w1g4 / 256, 256>>>(Wgx + (size_t)H_ * IN_, 5, w1g4);
    k_split16<<<w1g4 / 256, 256>>>(Wzx, 6, w1g4);
    k_split16<<<w1g4 / 256, 256>>>(Wrx, 7, w1g4);
    k_split16<<<w1g4 / 256, 256>>>(Wgx, 8, w1g4);
    k_split16<<<w1g4 / 256, 256>>>(Wo, 9, w1g4);

    k_prep<<<(B_ * H_) / 256, 256>>>(h0);

    // layer-1 x-projections (single-fp16 GEMMs, weights selected device-side)
    dim3 tgrid(1024 / 64, M_ / 128);   // (16, 128)
    k_hmma16<<<tgrid, 256>>>(0, bz, 0);
    k_hmma16<<<tgrid, 256>>>(1, br, H_);
    k_hmma16<<<tgrid, 256>>>(2, bg, 2 * H_);

    // wavefront recurrence + fused output projection: ONE launch
    k_gru_wave<<<NBLK, 256, SMEMR>>>(h0, bz, br, bg, bo, y_out, hid_out);
}

// round 17
// speedup vs baseline: 1.9173x; 1.0344x over previous
#include <cuda_runtime.h>
#include <cuda_fp16.h>
#include <math.h>
#include <stdint.h>

// ---------------------------------------------------------------------------
// MultilayerGRU: B=32, S=512, I=H=O=1024, L=2
// R17 = R16 (proven 6.21ms) + non-wave consolidation:
//  - k_hmma3: the 3 x-projection GEMMs fused into ONE launch sharing the
//    staged A (x) tile -> 3x less A traffic, 3x better A-LDS amortization.
//  - k_split_all: all 10 weight-split launches merged into one.
// Wave kernel byte-identical to R16.
// ---------------------------------------------------------------------------

#define B_  32
#define S_  512
#define IN_ 1024
#define H_  1024
#define OUT_ 1024
#define L_  2
#define M_  (B_ * S_)      /* 16384 */
#define N3_ (3 * H_)       /* 3072  */
#define NBLK 128

// ---------------- device scratch ------------------------------------------
__device__ float g_gx[(size_t)M_ * N3_];   // layer-1 x-projections

__device__ __align__(16) unsigned short g_h1f[B_ * H_];   // h1 fp16
__device__ __align__(16) unsigned short g_h2f[B_ * H_];   // h2 fp16
__device__ __align__(16) unsigned short g_rh1f[B_ * H_];  // r1*h1 fp16
__device__ __align__(16) unsigned short g_rh2f[B_ * H_];  // r2*h2 fp16

__device__ __align__(16) unsigned short g_xf[(size_t)M_ * IN_];   // x fp16

// fp16 weights
__device__ __align__(16) unsigned short g_wzx1f[(size_t)H_ * IN_];
__device__ __align__(16) unsigned short g_wrx1f[(size_t)H_ * IN_];
__device__ __align__(16) unsigned short g_wgx1f[(size_t)H_ * IN_];
__device__ __align__(16) unsigned short g_wzhf[(size_t)L_ * H_ * H_];
__device__ __align__(16) unsigned short g_wrhf[(size_t)L_ * H_ * H_];
__device__ __align__(16) unsigned short g_wghf[(size_t)L_ * H_ * H_];
__device__ __align__(16) unsigned short g_wzx2f[(size_t)H_ * H_];
__device__ __align__(16) unsigned short g_wrx2f[(size_t)H_ * H_];
__device__ __align__(16) unsigned short g_wgx2f[(size_t)H_ * H_];
__device__ __align__(16) unsigned short g_wohf[(size_t)OUT_ * H_];  // Wo hi
__device__ __align__(16) unsigned short g_wolf[(size_t)OUT_ * H_];  // Wo lo

// flat grid barrier (reset by k_prep)
__device__ unsigned g_bar_count;
__device__ volatile unsigned g_bar_gen;

__device__ __forceinline__ void grid_sync() {
    __syncthreads();
    if (threadIdx.x == 0) {
        __threadfence();
        unsigned gen = g_bar_gen;
        if (atomicAdd(&g_bar_count, 1u) == NBLK - 1u) {
            g_bar_count = 0;
            __threadfence();
            g_bar_gen = gen + 1u;
        } else {
            while (g_bar_gen == gen) { }
        }
    }
    __syncthreads();
}

// ---------------------------------------------------------------------------
__device__ __forceinline__ void split16(float v, unsigned short& h, unsigned short& l) {
    __half hh = __float2half(v);
    float r = v - __half2float(hh);
    h = __half_as_ushort(hh);
    l = __half_as_ushort(__float2half(r));
}

__device__ __forceinline__ void mma_f16(float* c, const uint32_t* a, const uint32_t* b) {
    asm volatile(
        "mma.sync.aligned.m16n8k16.row.col.f32.f16.f16.f32 "
        "{%0,%1,%2,%3}, {%4,%5,%6,%7}, {%8,%9}, {%0,%1,%2,%3};"
        : "+f"(c[0]), "+f"(c[1]), "+f"(c[2]), "+f"(c[3])
        : "r"(a[0]), "r"(a[1]), "r"(a[2]), "r"(a[3]), "r"(b[0]), "r"(b[1]));
}

__device__ __forceinline__ float sigmoidf_(float x) {
    return 1.f / (1.f + expf(-x));
}

// ---------------------------------------------------------------------------
// x[b][t][i] -> fp16 [t*B+b][i]
// ---------------------------------------------------------------------------
__global__ void k_transpose_x(const float* __restrict__ x) {
    int row = blockIdx.x;
    int t = row / B_;
    int b = row % B_;
    const float4* src = (const float4*)(x + ((size_t)b * S_ + t) * IN_);
    ushort4* dh = (ushort4*)(g_xf + (size_t)row * IN_);
    for (int i = threadIdx.x; i < IN_ / 4; i += blockDim.x) {
        float4 v = src[i];
        ushort4 h;
        h.x = __half_as_ushort(__float2half(v.x));
        h.y = __half_as_ushort(__float2half(v.y));
        h.z = __half_as_ushort(__float2half(v.z));
        h.w = __half_as_ushort(__float2half(v.w));
        dh[i] = h;
    }
}

// ---------------------------------------------------------------------------
// k_split_all: ALL weight conversions in one launch (1 quad per thread).
// Ranges (quads): [0, 3*Q1): Wzh/Wrh/Wgh -> fp16
//                 [3*Q1, 3*Q1+3*Q2): layer2 x-weights
//                 [+3*Q2): layer1 x-weights
//                 [+Q2): Wo -> hi/lo
// ---------------------------------------------------------------------------
#define Q1 524288   /* L*H*H/4  */
#define Q2 262144   /* H*H/4    */
#define QTOT (3 * Q1 + 6 * Q2 + Q2)   /* 3407872 */

__global__ void k_split_all(
    const float* __restrict__ Wzx, const float* __restrict__ Wzh,
    const float* __restrict__ Wrx, const float* __restrict__ Wrh,
    const float* __restrict__ Wgx, const float* __restrict__ Wgh,
    const float* __restrict__ Wo)
{
    int idx = blockIdx.x * 256 + threadIdx.x;
    if (idx >= QTOT) return;

    const float* src;
    unsigned short* dst;
    int i;

    if (idx < 3 * Q1) {
        int which = idx >> 19;            // /Q1
        i = idx & (Q1 - 1);
        src = (which == 0) ? Wzh : (which == 1) ? Wrh : Wgh;
        dst = (which == 0) ? g_wzhf : (which == 1) ? g_wrhf : g_wghf;
    } else if (idx < 3 * Q1 + 3 * Q2) {
        int r = idx - 3 * Q1;
        int which = r >> 18;              // /Q2
        i = r & (Q2 - 1);
        src = ((which == 0) ? Wzx : (which == 1) ? Wrx : Wgx) + (size_t)H_ * IN_;
        dst = (which == 0) ? g_wzx2f : (which == 1) ? g_wrx2f : g_wgx2f;
    } else if (idx < 3 * Q1 + 6 * Q2) {
        int r = idx - 3 * Q1 - 3 * Q2;
        int which = r >> 18;
        i = r & (Q2 - 1);
        src = (which == 0) ? Wzx : (which == 1) ? Wrx : Wgx;
        dst = (which == 0) ? g_wzx1f : (which == 1) ? g_wrx1f : g_wgx1f;
    } else {
        i = idx - 3 * Q1 - 6 * Q2;
        float4 v = ((const float4*)Wo)[i];
        ushort4 h, l;
        split16(v.x, h.x, l.x);
        split16(v.y, h.y, l.y);
        split16(v.z, h.z, l.z);
        split16(v.w, h.w, l.w);
        ((ushort4*)g_wohf)[i] = h;
        ((ushort4*)g_wolf)[i] = l;
        return;
    }

    float4 v = ((const float4*)src)[i];
    ushort4 h;
    h.x = __half_as_ushort(__float2half(v.x));
    h.y = __half_as_ushort(__float2half(v.y));
    h.z = __half_as_ushort(__float2half(v.z));
    h.w = __half_as_ushort(__float2half(v.w));
    ((ushort4*)dst)[i] = h;
}

// ---------------------------------------------------------------------------
// k_prep: fp16 h states from h0; reset barrier.
// ---------------------------------------------------------------------------
__global__ void k_prep(const float* __restrict__ h0) {
    int idx = blockIdx.x * blockDim.x + threadIdx.x;  // [0, B*H)
    if (idx == 0) { g_bar_count = 0; g_bar_gen = 0; }
    int b = idx / H_;
    int c = idx % H_;
    g_h1f[idx] = __half_as_ushort(__float2half(h0[((size_t)b * L_ + 0) * H_ + c]));
    g_h2f[idx] = __half_as_ushort(__float2half(h0[((size_t)b * L_ + 1) * H_ + c]));
}

// ---------------------------------------------------------------------------
// k_hmma3: ALL THREE x-projection GEMMs in one launch, sharing staged A.
//   g_gx[m][w*1024 + n] = sum_k x[m][k]*Wxw[n][k] + biasw[n], w in {z,r,g}.
//   Tile 128x64 per weight set, BK=32, 8 warps, A staged once per chunk.
// ---------------------------------------------------------------------------
#define HMP 40

__global__ void __launch_bounds__(256) k_hmma3(
    const float* __restrict__ bz, const float* __restrict__ br,
    const float* __restrict__ bg)
{
    __shared__ __align__(16) unsigned short As[128 * HMP];
    __shared__ __align__(16) unsigned short Bs[3][64 * HMP];

    const int tid = threadIdx.x;
    const int m0 = blockIdx.y * 128, n0 = blockIdx.x * 64;

    const unsigned short* A = g_xf;

    const int ar0 = (2 * tid) >> 2,     au0 = (2 * tid) & 3;
    const int ar1 = (2 * tid + 1) >> 2, au1 = (2 * tid + 1) & 3;
    const int br_ = tid >> 2,           bu  = tid & 3;

    const int warp = tid >> 5, lane = tid & 31;
    const int g = lane >> 2, tg = lane & 3;
    const int wm = warp >> 1, wn = warp & 1;

    float acc[3][2][4][4];
#pragma unroll
    for (int w = 0; w < 3; w++)
#pragma unroll
        for (int mt = 0; mt < 2; mt++)
#pragma unroll
            for (int nt = 0; nt < 4; nt++)
#pragma unroll
                for (int i = 0; i < 4; i++) acc[w][mt][nt][i] = 0.f;

    const uint32_t* Aw = (const uint32_t*)As;

    uint4 va0, va1, vb0, vb1, vb2;
    va0 = *(const uint4*)(A + (size_t)(m0 + ar0) * 1024 + au0 * 8);
    va1 = *(const uint4*)(A + (size_t)(m0 + ar1) * 1024 + au1 * 8);
    vb0 = *(const uint4*)(g_wzx1f + (size_t)(n0 + br_) * 1024 + bu * 8);
    vb1 = *(const uint4*)(g_wrx1f + (size_t)(n0 + br_) * 1024 + bu * 8);
    vb2 = *(const uint4*)(g_wgx1f + (size_t)(n0 + br_) * 1024 + bu * 8);

    for (int kc = 0; kc < 32; kc++) {
        __syncthreads();
        *(uint4*)(As + ar0 * HMP + au0 * 8) = va0;
        *(uint4*)(As + ar1 * HMP + au1 * 8) = va1;
        *(uint4*)(Bs[0] + br_ * HMP + bu * 8) = vb0;
        *(uint4*)(Bs[1] + br_ * HMP + bu * 8) = vb1;
        *(uint4*)(Bs[2] + br_ * HMP + bu * 8) = vb2;
        if (kc + 1 < 32) {
            int ko = (kc + 1) * 32;
            va0 = *(const uint4*)(A + (size_t)(m0 + ar0) * 1024 + ko + au0 * 8);
            va1 = *(const uint4*)(A + (size_t)(m0 + ar1) * 1024 + ko + au1 * 8);
            vb0 = *(const uint4*)(g_wzx1f + (size_t)(n0 + br_) * 1024 + ko + bu * 8);
            vb1 = *(const uint4*)(g_wrx1f + (size_t)(n0 + br_) * 1024 + ko + bu * 8);
            vb2 = *(const uint4*)(g_wgx1f + (size_t)(n0 + br_) * 1024 + ko + bu * 8);
        }
        __syncthreads();

#pragma unroll
        for (int ks = 0; ks < 2; ks++) {
            const int kw = ks * 8 + tg;
            uint32_t af[2][4];
#pragma unroll
            for (int mt = 0; mt < 2; mt++) {
                int rb = (wm * 32 + mt * 16 + g) * 20 + kw;
                af[mt][0] = Aw[rb];
                af[mt][1] = Aw[rb + 160];
                af[mt][2] = Aw[rb + 4];
                af[mt][3] = Aw[rb + 164];
            }
#pragma unroll
            for (int w = 0; w < 3; w++) {
                const uint32_t* Bw = (const uint32_t*)Bs[w];
                uint32_t bf[4][2];
#pragma unroll
                for (int nt = 0; nt < 4; nt++) {
                    int rb = (wn * 32 + nt * 8 + g) * 20 + kw;
                    bf[nt][0] = Bw[rb];
                    bf[nt][1] = Bw[rb + 4];
                }
#pragma unroll
                for (int mt = 0; mt < 2; mt++)
#pragma unroll
                    for (int nt = 0; nt < 4; nt++)
                        mma_f16(acc[w][mt][nt], af[mt], bf[nt]);
            }
        }
    }

#pragma unroll
    for (int w = 0; w < 3; w++) {
        const float* bias = (w == 0) ? bz : (w == 1) ? br : bg;
        const int col0 = w * 1024;
#pragma unroll
        for (int mt = 0; mt < 2; mt++) {
#pragma unroll
            for (int nt = 0; nt < 4; nt++) {
                int mrow = m0 + wm * 32 + mt * 16 + g;
                int ncol = n0 + wn * 32 + nt * 8 + tg * 2;
                float bx = bias[ncol], by = bias[ncol + 1];
#pragma unroll
                for (int half = 0; half < 2; half++) {
                    int m = mrow + half * 8;
                    float2 o;
                    o.x = acc[w][mt][nt][half * 2 + 0] + bx;
                    o.y = acc[w][mt][nt][half * 2 + 1] + by;
                    *(float2*)(g_gx + (size_t)m * N3_ + col0 + ncol) = o;
                }
            }
        }
    }
}

// ---------------------------------------------------------------------------
// Wavefront recurrence + fused output projection (byte-identical to R16).
// ---------------------------------------------------------------------------
#define SW_PW 516
#define TILE_B (32 * SW_PW * 4)             /* 66048 per tile */
#define WX_PITCH 516
#define WX_SET (8 * WX_PITCH)
#define WX_B (3 * WX_SET * 4)               /* 49536 */
#define RED_STRIDE 42
#define RED_B (8 * 32 * RED_STRIDE * 4)     /* 43008 */
#define SMEMR (2 * TILE_B + WX_B + RED_B)   /* 224640 */

__device__ __forceinline__ void stage_warp(
    const unsigned short* __restrict__ gsrc, uint32_t* __restrict__ s,
    int warp, int lane)
{
    const int colq = warp * 16 + (lane & 15);
    const int rb = lane >> 4;
#pragma unroll
    for (int half = 0; half < 2; half++) {
        uint4 v[8];
#pragma unroll
        for (int it = 0; it < 8; it++) {
            int row = (half * 8 + it) * 2 + rb;
            v[it] = __ldcg((const uint4*)(gsrc + (size_t)row * H_) + colq);
        }
#pragma unroll
        for (int it = 0; it < 8; it++) {
            int row = (half * 8 + it) * 2 + rb;
            *(uint4*)(s + row * SW_PW + colq * 4) = v[it];
        }
    }
}

#define LOAD_AFRAG(dst, tile, kw)                                  \
    do {                                                           \
        _Pragma("unroll")                                          \
        for (int mt = 0; mt < 2; mt++) {                           \
            const uint32_t* b0 = (tile) + (mt * 16 + g) * SW_PW;   \
            const uint32_t* b1 = b0 + 8 * SW_PW;                   \
            (dst)[mt][0] = b0[(kw)];                               \
            (dst)[mt][1] = b1[(kw)];                               \
            (dst)[mt][2] = b0[(kw) + 4];                           \
            (dst)[mt][3] = b1[(kw) + 4];                           \
        }                                                          \
    } while (0)

__global__ void __launch_bounds__(256, 1) k_gru_wave(
    const float* __restrict__ h0,
    const float* __restrict__ bz, const float* __restrict__ br,
    const float* __restrict__ bg, const float* __restrict__ bo,
    float* __restrict__ y_out, float* __restrict__ hid_out)
{
    extern __shared__ char smem[];
    uint32_t* s_t1 = (uint32_t*)smem;                          // h1/rh1 tile
    uint32_t* s_t2 = (uint32_t*)(smem + TILE_B);               // h2/rh2 tile
    uint32_t* s_wx = (uint32_t*)(smem + 2 * TILE_B);           // x2 weights
    float*    red  = (float*)(smem + 2 * TILE_B + WX_B);       // [8][32][42]

    const int tid = threadIdx.x;
    const int warp = tid >> 5, lane = tid & 31;
    const int g = lane >> 2, tg = lane & 3;

    const int c0 = blockIdx.x * 8;

    // ---- layer2 x-weights -> smem ----
    {
        const uint32_t* wz = (const uint32_t*)(g_wzx2f + (size_t)c0 * H_);
        const uint32_t* wr = (const uint32_t*)(g_wrx2f + (size_t)c0 * H_);
        const uint32_t* wg = (const uint32_t*)(g_wgx2f + (size_t)c0 * H_);
        for (int idx = tid; idx < 8 * 512; idx += 256) {
            int row = idx >> 9, word = idx & 511;
            s_wx[0 * WX_SET + row * WX_PITCH + word] = wz[row * 512 + word];
            s_wx[1 * WX_SET + row * WX_PITCH + word] = wr[row * 512 + word];
            s_wx[2 * WX_SET + row * WX_PITCH + word] = wg[row * 512 + word];
        }
    }
    __syncthreads();   // s_wx visible to all warps before first use

    // ---- register weight fragments ----
    uint32_t wz1[8][2], wr1[8][2], wg1[8][2];
    uint32_t wz2[8][2], wr2[8][2], wg2[8][2];
    uint32_t woh[8][2], wol[8][2];
    {
        const size_t r1 = (size_t)(c0 + g) * H_;            // layer1 rows
        const size_t r2 = (size_t)H_ * H_ + r1;             // layer2 rows
#pragma unroll
        for (int ks = 0; ks < 8; ks++) {
            int kw = warp * 64 + ks * 8 + tg;
            wz1[ks][0] = ((const uint32_t*)(g_wzhf))[r1 / 2 + kw];
            wz1[ks][1] = ((const uint32_t*)(g_wzhf))[r1 / 2 + kw + 4];
            wr1[ks][0] = ((const uint32_t*)(g_wrhf))[r1 / 2 + kw];
            wr1[ks][1] = ((const uint32_t*)(g_wrhf))[r1 / 2 + kw + 4];
            wg1[ks][0] = ((const uint32_t*)(g_wghf))[r1 / 2 + kw];
            wg1[ks][1] = ((const uint32_t*)(g_wghf))[r1 / 2 + kw + 4];
            wz2[ks][0] = ((const uint32_t*)(g_wzhf))[r2 / 2 + kw];
            wz2[ks][1] = ((const uint32_t*)(g_wzhf))[r2 / 2 + kw + 4];
            wr2[ks][0] = ((const uint32_t*)(g_wrhf))[r2 / 2 + kw];
            wr2[ks][1] = ((const uint32_t*)(g_wrhf))[r2 / 2 + kw + 4];
            wg2[ks][0] = ((const uint32_t*)(g_wghf))[r2 / 2 + kw];
            wg2[ks][1] = ((const uint32_t*)(g_wghf))[r2 / 2 + kw + 4];
            woh[ks][0] = ((const uint32_t*)(g_wohf))[r1 / 2 + kw];
            woh[ks][1] = ((const uint32_t*)(g_wohf))[r1 / 2 + kw + 4];
            wol[ks][0] = ((const uint32_t*)(g_wolf))[r1 / 2 + kw];
            wol[ks][1] = ((const uint32_t*)(g_wolf))[r1 / 2 + kw + 4];
        }
    }

    // ---- per-thread state: (b=eb, col=j) ----
    const int eb = tid >> 3, ec = tid & 7;
    const int j = c0 + ec;

    float hv1 = h0[((size_t)eb * L_ + 0) * H_ + j];
    float hv2 = h0[((size_t)eb * L_ + 1) * H_ + j];
    const float bz2j = bz[H_ + j], br2j = br[H_ + j], bg2j = bg[H_ + j];
    const float boj = bo[j];

    float gxz1 = __ldcg(&g_gx[(size_t)eb * N3_ + j]);
    float gxr1 = __ldcg(&g_gx[(size_t)eb * N3_ + H_ + j]);

    float z1reg = 0.f, z2reg = 0.f, vgx2 = 0.f;
    float yacc[2][4];

    for (int k = 0; k <= S_ + 1; k++) {
        const bool l1 = (k < S_);
        const bool l2 = (k >= 1 && k <= S_);
        const bool ly = (k >= 2);

        float gxg1 = 0.f;
        if (l1) gxg1 = __ldcg(&g_gx[((size_t)k * B_ + eb) * N3_ + 2 * H_ + j]);

        // ================= phase A =================
        stage_warp(g_h1f, s_t1, warp, lane);
        stage_warp(g_h2f, s_t2, warp, lane);
        __syncwarp();

        float aZ1[2][4], aR1[2][4], aZ2[2][4], aR2[2][4], aG2[2][4];
#pragma unroll
        for (int mt = 0; mt < 2; mt++)
#pragma unroll
            for (int i = 0; i < 4; i++) {
                aZ1[mt][i] = 0.f; aR1[mt][i] = 0.f;
                aZ2[mt][i] = 0.f; aR2[mt][i] = 0.f; aG2[mt][i] = 0.f;
                yacc[mt][i] = 0.f;
            }

#pragma unroll
        for (int ks = 0; ks < 8; ks++) {
            const int kw = warp * 64 + ks * 8 + tg;
            uint32_t a1[2][4], a2[2][4];
            LOAD_AFRAG(a1, s_t1, kw);
            LOAD_AFRAG(a2, s_t2, kw);
            uint32_t wzx[2], wrx[2], wgx[2];
            {
                int wo = g * WX_PITCH + kw;
                wzx[0] = s_wx[wo];              wzx[1] = s_wx[wo + 4];
                wrx[0] = s_wx[WX_SET + wo];     wrx[1] = s_wx[WX_SET + wo + 4];
                wgx[0] = s_wx[2 * WX_SET + wo]; wgx[1] = s_wx[2 * WX_SET + wo + 4];
            }
#pragma unroll
            for (int mt = 0; mt < 2; mt++) {
                mma_f16(aZ1[mt], a1[mt], wz1[ks]);
                mma_f16(aR1[mt], a1[mt], wr1[ks]);
                mma_f16(aZ2[mt], a1[mt], wzx);
                mma_f16(aZ2[mt], a2[mt], wz2[ks]);
                mma_f16(aR2[mt], a1[mt], wrx);
                mma_f16(aR2[mt], a2[mt], wr2[ks]);
                mma_f16(aG2[mt], a1[mt], wgx);
                mma_f16(yacc[mt], a2[mt], woh[ks]);
                mma_f16(yacc[mt], a2[mt], wol[ks]);
            }
        }

        // red: groups z1(0) r1(8) z2(16) r2(24) gx2(32)
#pragma unroll
        for (int mt = 0; mt < 2; mt++)
#pragma unroll
            for (int i = 0; i < 4; i++) {
                int brow = mt * 16 + g + (i >> 1) * 8;
                int cc = tg * 2 + (i & 1);
                float* rp = &red[(warp * 32 + brow) * RED_STRIDE + cc];
                rp[0]  = aZ1[mt][i];
                rp[8]  = aR1[mt][i];
                rp[16] = aZ2[mt][i];
                rp[24] = aR2[mt][i];
                rp[32] = aG2[mt][i];
            }
        __syncthreads();

        {
            if (l1) {
                float vz = 0.f, vr = 0.f;
#pragma unroll
                for (int w = 0; w < 8; w++) {
                    const float* rp = &red[(w * 32 + eb) * RED_STRIDE + ec];
                    vz += rp[0];
                    vr += rp[8];
                }
                z1reg = sigmoidf_(vz + gxz1);
                float r1 = sigmoidf_(vr + gxr1);
                g_rh1f[eb * H_ + j] = __half_as_ushort(__float2half(r1 * hv1));
            }
            if (l2) {
                float vz = 0.f, vr = 0.f, vg = 0.f;
#pragma unroll
                for (int w = 0; w < 8; w++) {
                    const float* rp = &red[(w * 32 + eb) * RED_STRIDE + ec];
                    vz += rp[16];
                    vr += rp[24];
                    vg += rp[32];
                }
                z2reg = sigmoidf_(vz + bz2j);
                float r2 = sigmoidf_(vr + br2j);
                g_rh2f[eb * H_ + j] = __half_as_ushort(__float2half(r2 * hv2));
                vgx2 = vg;
            }
        }

        grid_sync();

        // ================= phase B =================
        stage_warp(g_rh1f, s_t1, warp, lane);
        stage_warp(g_rh2f, s_t2, warp, lane);
        __syncwarp();

        float aG1[2][4], bG2[2][4];
#pragma unroll
        for (int mt = 0; mt < 2; mt++)
#pragma unroll
            for (int i = 0; i < 4; i++) { aG1[mt][i] = 0.f; bG2[mt][i] = 0.f; }

#pragma unroll
        for (int ks = 0; ks < 8; ks++) {
            const int kw = warp * 64 + ks * 8 + tg;
            uint32_t a1[2][4], a2[2][4];
            LOAD_AFRAG(a1, s_t1, kw);
            LOAD_AFRAG(a2, s_t2, kw);
#pragma unroll
            for (int mt = 0; mt < 2; mt++) {
                mma_f16(aG1[mt], a1[mt], wg1[ks]);
                mma_f16(bG2[mt], a2[mt], wg2[ks]);
            }
        }

        // red: g1(0) g2(8) y(16)
#pragma unroll
        for (int mt = 0; mt < 2; mt++)
#pragma unroll
            for (int i = 0; i < 4; i++) {
                int brow = mt * 16 + g + (i >> 1) * 8;
                int cc = tg * 2 + (i & 1);
                float* rp = &red[(warp * 32 + brow) * RED_STRIDE + cc];
                rp[0]  = aG1[mt][i];
                rp[8]  = bG2[mt][i];
                rp[16] = yacc[mt][i];
            }
        __syncthreads();

        {
            if (l1) {
                float v = 0.f;
#pragma unroll
                for (int w = 0; w < 8; w++)
                    v += red[(w * 32 + eb) * RED_STRIDE + ec];
                float gv = tanhf(v + gxg1);
                hv1 = fmaf(z1reg, gv - hv1, hv1);
                g_h1f[eb * H_ + j] = __half_as_ushort(__float2half(hv1));
                if (hid_out && k == S_ - 1)
                    hid_out[((size_t)eb * L_ + 0) * H_ + j] = hv1;
            }
            if (l2) {
                float v = 0.f;
#pragma unroll
                for (int w = 0; w < 8; w++)
                    v += red[(w * 32 + eb) * RED_STRIDE + 8 + ec];
                float gv = tanhf(v + vgx2 + bg2j);
                hv2 = fmaf(z2reg, gv - hv2, hv2);
                g_h2f[eb * H_ + j] = __half_as_ushort(__float2half(hv2));
                if (hid_out && k == S_)
                    hid_out[((size_t)eb * L_ + 1) * H_ + j] = hv2;
            }
            if (ly) {
                float v = 0.f;
#pragma unroll
                for (int w = 0; w < 8; w++)
                    v += red[(w * 32 + eb) * RED_STRIDE + 16 + ec];
                y_out[((size_t)eb * S_ + (k - 2)) * OUT_ + j] = v + boj;
            }
        }

        // prefetch next phase-A gx (constant data)
        if (k + 1 < S_) {
            gxz1 = __ldcg(&g_gx[((size_t)(k + 1) * B_ + eb) * N3_ + j]);
            gxr1 = __ldcg(&g_gx[((size_t)(k + 1) * B_ + eb) * N3_ + H_ + j]);
        }

        grid_sync();
    }
}

// ---------------------------------------------------------------------------
// Launch
// ---------------------------------------------------------------------------
extern "C" void kernel_launch(void* const* d_in, const int* in_sizes, int n_in,
                              void* d_out, int out_size) {
    (void)in_sizes; (void)n_in;
    const float* x   = (const float*)d_in[0];
    const float* h0  = (const float*)d_in[1];
    const float* Wzx = (const float*)d_in[2];
    const float* bz  = (const float*)d_in[3];
    const float* Wzh = (const float*)d_in[4];
    const float* Wrx = (const float*)d_in[5];
    const float* br  = (const float*)d_in[6];
    const float* Wrh = (const float*)d_in[7];
    const float* Wgx = (const float*)d_in[8];
    const float* bg  = (const float*)d_in[9];
    const float* Wgh = (const float*)d_in[10];
    const float* Wo  = (const float*)d_in[11];
    const float* bo  = (const float*)d_in[12];

    float* out = (float*)d_out;
    float* y_out = out;
    const long long need = (long long)B_ * S_ * OUT_ + (long long)B_ * L_ * H_;
    float* hid_out = ((long long)out_size >= need) ? out + (size_t)B_ * S_ * OUT_
                                                   : nullptr;

    cudaFuncSetAttribute(k_gru_wave,
        cudaFuncAttributeMaxDynamicSharedMemorySize, SMEMR);

    // operand prep (all fp16): 3 launches total
    k_transpose_x<<<M_, 256>>>(x);
    k_split_all<<<(QTOT + 255) / 256, 256>>>(Wzx, Wzh, Wrx, Wrh, Wgx, Wgh, Wo);
    k_prep<<<(B_ * H_) / 256, 256>>>(h0);

    // layer-1 x-projections: ONE fused GEMM launch (A staged once)
    dim3 tgrid(1024 / 64, M_ / 128);   // (16, 128)
    k_hmma3<<<tgrid, 256>>>(bz, br, bg);

    // wavefront recurrence + fused output projection: ONE launch
    k_gru_wave<<<NBLK, 256, SMEMR>>>(h0, bz, br, bg, bo, y_out, hid_out);
}